// round 3
// baseline (speedup 1.0000x reference)
#include <cuda_runtime.h>
#include <math.h>

// ---------------- problem constants ----------------
#define TT 128
#define BB 32
#define NN (TT*BB)      // 4096
#define HH 128
#define AA 6

// output layout: logits (4096*6) | value (4096) | hT (32*128) | cT (32*128)
#define OFF_LOGITS 0
#define OFF_VALUE  24576
#define OFF_HT     28672
#define OFF_CT     32768

// ---------------- device scratch ----------------
__device__ float g_z1[NN*32*20*20];     // conv1 out
__device__ float g_z2[NN*64*9*9];       // conv2 out
__device__ float g_z3[NN*3136];         // conv3 out, flattened torch order
__device__ float g_hidden[NN*512];      // fc out
__device__ float g_gx[NN*512];          // gates_x
__device__ float g_hs[NN*HH];           // per-step hidden outputs
__device__ float g_hA[BB*HH];           // double-buffered h, layout [j*32+b]
__device__ float g_hB[BB*HH];
__device__ float g_w1t[64*32];          // [ky*8+kx][oc]
__device__ float g_w2t[512*64];         // [ic*16+ky*4+kx][oc]
__device__ float g_w3t[576*64];         // [ic*9+ky*3+kx][oc]

__device__ int g_bar_cnt;               // zero-init; returns to 0 after each barrier
__device__ volatile unsigned g_bar_gen; // monotonic; equality-compared -> replay safe

__device__ __forceinline__ float sigm(float x) { return 1.f / (1.f + expf(-x)); }

// ---------------- weight pre-transpose ----------------
__global__ void prep_kernel(const float* __restrict__ W1,
                            const float* __restrict__ W2,
                            const float* __restrict__ W3) {
    int i = blockIdx.x * blockDim.x + threadIdx.x;
    int stride = gridDim.x * blockDim.x;
    for (int t = i; t < 2048; t += stride) {          // W1: (32,1,8,8)
        int oc = t / 64, p = t % 64;
        g_w1t[p*32 + oc] = W1[oc*64 + p];
    }
    for (int t = i; t < 32768; t += stride) {         // W2: (64,32,4,4)
        int oc = t / 512, p = t % 512;
        g_w2t[p*64 + oc] = W2[oc*512 + p];
    }
    for (int t = i; t < 36864; t += stride) {         // W3: (64,64,3,3)
        int oc = t / 576, p = t % 576;
        g_w3t[p*64 + oc] = W3[oc*576 + p];
    }
}

// ---------------- conv1: (1,84,84) -> (32,20,20), k8 s4, x/255, relu ----------------
// 4096 blocks x 320 threads. thread = (ocg 0..7, oy 0..19, oxhalf 0..1), 4 oc x 10 ox per thread.
__global__ void __launch_bounds__(320, 1)
conv1_kernel(const float* __restrict__ x, const float* __restrict__ b1) {
    __shared__ float img[84*84];
    __shared__ float w_s[64*32];
    int n = blockIdx.x, tid = threadIdx.x;

    for (int i = tid; i < 84*84; i += 320) img[i] = x[n*7056 + i] * (1.f/255.f);
    for (int i = tid; i < 2048;  i += 320) w_s[i] = g_w1t[i];
    __syncthreads();

    int ocg = tid & 7;
    int oy  = (tid >> 3) % 20;
    int oxh = tid / 160;
    int oc0 = ocg * 4;

    float acc[4][10];
    #pragma unroll
    for (int m = 0; m < 4; m++)
        #pragma unroll
        for (int o = 0; o < 10; o++) acc[m][o] = 0.f;

    #pragma unroll
    for (int ky = 0; ky < 8; ky++) {
        const float* row = &img[(oy*4 + ky)*84 + oxh*40];
        float in_r[44];
        #pragma unroll
        for (int c = 0; c < 11; c++) {
            float4 v = *(const float4*)&row[c*4];
            in_r[c*4+0] = v.x; in_r[c*4+1] = v.y; in_r[c*4+2] = v.z; in_r[c*4+3] = v.w;
        }
        #pragma unroll
        for (int kx = 0; kx < 8; kx++) {
            float4 w4 = *(const float4*)&w_s[(ky*8 + kx)*32 + oc0];
            #pragma unroll
            for (int ox = 0; ox < 10; ox++) {
                float iv = in_r[ox*4 + kx];
                acc[0][ox] += w4.x * iv;
                acc[1][ox] += w4.y * iv;
                acc[2][ox] += w4.z * iv;
                acc[3][ox] += w4.w * iv;
            }
        }
    }
    #pragma unroll
    for (int m = 0; m < 4; m++) {
        int oc = oc0 + m;
        float bv = b1[oc];
        #pragma unroll
        for (int ox = 0; ox < 10; ox++) {
            float v = acc[m][ox] + bv;
            g_z1[((n*32 + oc)*20 + oy)*20 + oxh*10 + ox] = v > 0.f ? v : 0.f;
        }
    }
}

// ---------------- conv2: (32,20,20) -> (64,9,9), k4 s2, relu ----------------
// 4096 blocks x 160 threads (144 compute). thread = (ocg 0..15, oy 0..8), 4 oc x 9 ox.
__global__ void __launch_bounds__(160, 2)
conv2_kernel(const float* __restrict__ b2) {
    __shared__ float in_s[8*400];       // ic-chunk of 8, [ic][iy*20+ix]
    __shared__ float w_s[8*16*64];      // [ic*16 + ky*4 + kx][oc]
    int n = blockIdx.x, tid = threadIdx.x;
    int ocg = tid & 15;
    int oy  = tid >> 4;                 // valid when tid < 144
    int oc0 = ocg * 4;

    float acc[4][9];
    #pragma unroll
    for (int m = 0; m < 4; m++)
        #pragma unroll
        for (int o = 0; o < 9; o++) acc[m][o] = 0.f;

    for (int icc = 0; icc < 4; icc++) {
        __syncthreads();
        for (int i = tid; i < 800; i += 160)
            *(float4*)&in_s[i*4] = *(const float4*)&g_z1[n*12800 + icc*3200 + i*4];
        for (int i = tid; i < 2048; i += 160)
            *(float4*)&w_s[i*4] = *(const float4*)&g_w2t[icc*8192 + i*4];
        __syncthreads();
        if (tid < 144) {
            #pragma unroll
            for (int ic = 0; ic < 8; ic++) {
                #pragma unroll
                for (int ky = 0; ky < 4; ky++) {
                    const float* row = &in_s[ic*400 + (oy*2 + ky)*20];
                    float in_r[20];
                    #pragma unroll
                    for (int c = 0; c < 5; c++) {
                        float4 v = *(const float4*)&row[c*4];
                        in_r[c*4+0] = v.x; in_r[c*4+1] = v.y; in_r[c*4+2] = v.z; in_r[c*4+3] = v.w;
                    }
                    #pragma unroll
                    for (int kx = 0; kx < 4; kx++) {
                        float4 w4 = *(const float4*)&w_s[(ic*16 + ky*4 + kx)*64 + oc0];
                        #pragma unroll
                        for (int ox = 0; ox < 9; ox++) {
                            float iv = in_r[ox*2 + kx];
                            acc[0][ox] += w4.x * iv;
                            acc[1][ox] += w4.y * iv;
                            acc[2][ox] += w4.z * iv;
                            acc[3][ox] += w4.w * iv;
                        }
                    }
                }
            }
        }
    }
    if (tid < 144) {
        #pragma unroll
        for (int m = 0; m < 4; m++) {
            int oc = oc0 + m;
            float bv = b2[oc];
            #pragma unroll
            for (int ox = 0; ox < 9; ox++) {
                float v = acc[m][ox] + bv;
                g_z2[((n*64 + oc)*9 + oy)*9 + ox] = v > 0.f ? v : 0.f;
            }
        }
    }
}

// ---------------- conv3: (64,9,9) -> (64,7,7), k3 s1, relu ----------------
// 4096 blocks x 128 threads (112 compute). thread = (ocg 0..15, oy 0..6), 4 oc x 7 ox.
__global__ void __launch_bounds__(128, 2)
conv3_kernel(const float* __restrict__ b3) {
    __shared__ float in_s[16*9*12];     // padded rows of 12
    __shared__ float w_s[16*9*64];      // [ic*9 + ky*3 + kx][oc]
    int n = blockIdx.x, tid = threadIdx.x;
    int ocg = tid & 15;
    int oy  = tid >> 4;                 // valid when tid < 112
    int oc0 = ocg * 4;

    float acc[4][7];
    #pragma unroll
    for (int m = 0; m < 4; m++)
        #pragma unroll
        for (int o = 0; o < 7; o++) acc[m][o] = 0.f;

    for (int icc = 0; icc < 4; icc++) {
        __syncthreads();
        for (int i = tid; i < 1296; i += 128) {
            int ic = i / 81, r = i % 81;
            in_s[ic*108 + (r/9)*12 + (r%9)] = g_z2[n*5184 + icc*1296 + i];
        }
        for (int i = tid; i < 2304; i += 128)
            *(float4*)&w_s[i*4] = *(const float4*)&g_w3t[icc*9216 + i*4];
        __syncthreads();
        if (tid < 112) {
            #pragma unroll
            for (int ic = 0; ic < 16; ic++) {
                #pragma unroll
                for (int ky = 0; ky < 3; ky++) {
                    const float* row = &in_s[ic*108 + (oy + ky)*12];
                    float in_r[9];
                    #pragma unroll
                    for (int c = 0; c < 9; c++) in_r[c] = row[c];
                    #pragma unroll
                    for (int kx = 0; kx < 3; kx++) {
                        float4 w4 = *(const float4*)&w_s[(ic*9 + ky*3 + kx)*64 + oc0];
                        #pragma unroll
                        for (int ox = 0; ox < 7; ox++) {
                            float iv = in_r[ox + kx];
                            acc[0][ox] += w4.x * iv;
                            acc[1][ox] += w4.y * iv;
                            acc[2][ox] += w4.z * iv;
                            acc[3][ox] += w4.w * iv;
                        }
                    }
                }
            }
        }
    }
    if (tid < 112) {
        #pragma unroll
        for (int m = 0; m < 4; m++) {
            int oc = oc0 + m;
            float bv = b3[oc];
            #pragma unroll
            for (int ox = 0; ox < 7; ox++) {
                float v = acc[m][ox] + bv;
                g_z3[n*3136 + oc*49 + oy*7 + ox] = v > 0.f ? v : 0.f;
            }
        }
    }
}

// ---------------- NT GEMM: C[M,N] = act(A[M,K] @ B[N,K]^T + bias[N]) ----------------
// 64x64 tile, 256 threads, 4x4 per thread, k-tile 16.
__global__ void __launch_bounds__(256, 4)
gemm_nt_kernel(const float* __restrict__ A, const float* __restrict__ B,
               const float* __restrict__ bias, float* __restrict__ C,
               int M, int N, int K, int relu) {
    __shared__ float As[16][64];
    __shared__ float Bs[16][64];
    int m0 = blockIdx.y * 64, n0 = blockIdx.x * 64;
    int tid = threadIdx.x;
    int tn = tid & 15, tm = tid >> 4;
    int lm = tid >> 2, lk = (tid & 3) * 4;

    float acc[4][4];
    #pragma unroll
    for (int i = 0; i < 4; i++)
        #pragma unroll
        for (int j = 0; j < 4; j++) acc[i][j] = 0.f;

    for (int k0 = 0; k0 < K; k0 += 16) {
        float4 av = *(const float4*)&A[(m0 + lm)*K + k0 + lk];
        float4 bv = *(const float4*)&B[(n0 + lm)*K + k0 + lk];
        As[lk+0][lm] = av.x; As[lk+1][lm] = av.y; As[lk+2][lm] = av.z; As[lk+3][lm] = av.w;
        Bs[lk+0][lm] = bv.x; Bs[lk+1][lm] = bv.y; Bs[lk+2][lm] = bv.z; Bs[lk+3][lm] = bv.w;
        __syncthreads();
        #pragma unroll
        for (int k = 0; k < 16; k++) {
            float4 a4 = *(const float4*)&As[k][tm*4];
            float4 b4 = *(const float4*)&Bs[k][tn*4];
            float am[4] = {a4.x, a4.y, a4.z, a4.w};
            float bn[4] = {b4.x, b4.y, b4.z, b4.w};
            #pragma unroll
            for (int i = 0; i < 4; i++)
                #pragma unroll
                for (int j = 0; j < 4; j++) acc[i][j] += am[i] * bn[j];
        }
        __syncthreads();
    }
    #pragma unroll
    for (int i = 0; i < 4; i++) {
        int m = m0 + tm*4 + i;
        #pragma unroll
        for (int j = 0; j < 4; j++) {
            int nn = n0 + tn*4 + j;
            float v = acc[i][j] + bias[nn];
            if (relu) v = v > 0.f ? v : 0.f;
            C[m*N + nn] = v;
        }
    }
}

// ---------------- persistent LSTM scan ----------------
#define NB_LSTM 32
// All threads fence (orders THEIR global writes to L2) before block arrival.
__device__ __forceinline__ void grid_barrier() {
    __threadfence();
    __syncthreads();
    if (threadIdx.x == 0) {
        unsigned gen = g_bar_gen;
        if (atomicAdd(&g_bar_cnt, 1) == NB_LSTM - 1) {
            atomicExch(&g_bar_cnt, 0);
            __threadfence();
            g_bar_gen = gen + 1;
        } else {
            while (g_bar_gen == gen) { __nanosleep(40); }
        }
        __threadfence();
    }
    __syncthreads();
}

// 32 blocks x 128 threads. Block q owns hidden units j in [q*4, q*4+4).
// Compute role: warp = gate (i,f,g,o), lane = batch; 4 accumulators (jl).
// Cross-block h traffic goes through __stcg/__ldcg (L2, coherent) — default LDG
// would hit stale per-SM L1 lines across grid-barrier steps.
__global__ void __launch_bounds__(128, 1)
lstm_kernel(const float* __restrict__ gx, const float* __restrict__ done,
            const float* __restrict__ h0, const float* __restrict__ c0,
            const float* __restrict__ W_hh, const float* __restrict__ b_hh,
            float* __restrict__ out) {
    __shared__ float w_s[4][128][4];   // [gate][k][jl]
    __shared__ float h_sm[128*32];     // [k*32+b], masked h
    __shared__ float gacc[4][4][32];   // [gate][jl][b]
    __shared__ float c_s[4][32];
    __shared__ float d_s[32];
    __shared__ float bb_s[4][4];

    int q = blockIdx.x, tid = threadIdx.x;
    int j0 = q * 4;
    int gate = tid >> 5;               // also serves as jl in the epilogue
    int b = tid & 31;

    for (int i = tid; i < 2048; i += 128) {
        int jl = i & 3, k = (i >> 2) & 127, g = i >> 9;
        w_s[g][k][jl] = W_hh[(g*128 + j0 + jl)*128 + k];
    }
    if (tid < 16) bb_s[tid >> 2][tid & 3] = b_hh[(tid >> 2)*128 + j0 + (tid & 3)];
    c_s[gate][b] = c0[b*128 + j0 + gate];
    __stcg(&g_hA[(j0 + gate)*32 + b], h0[b*128 + j0 + gate]);
    grid_barrier();

    float last_h = 0.f, last_c = 0.f;
    for (int t = 0; t < TT; t++) {
        const float* hr = (t & 1) ? g_hB : g_hA;
        float*       hw = (t & 1) ? g_hA : g_hB;
        if (tid < 32) d_s[tid] = done[t*32 + tid];
        __syncthreads();
        for (int i = tid; i < 4096; i += 128)
            h_sm[i] = __ldcg(&hr[i]) * (1.f - d_s[i & 31]);
        __syncthreads();

        const float* gxr = &gx[(t*32 + b)*512 + gate*128 + j0];
        float a0 = gxr[0] + bb_s[gate][0];
        float a1 = gxr[1] + bb_s[gate][1];
        float a2 = gxr[2] + bb_s[gate][2];
        float a3 = gxr[3] + bb_s[gate][3];
        #pragma unroll 8
        for (int k = 0; k < 128; k++) {
            float hv = h_sm[k*32 + b];
            float4 w4 = *(const float4*)&w_s[gate][k][0];
            a0 += w4.x * hv; a1 += w4.y * hv; a2 += w4.z * hv; a3 += w4.w * hv;
        }
        gacc[gate][0][b] = a0; gacc[gate][1][b] = a1;
        gacc[gate][2][b] = a2; gacc[gate][3][b] = a3;
        __syncthreads();

        // epilogue: thread = (jl=gate, b)
        float iv = gacc[0][gate][b], fv = gacc[1][gate][b];
        float gv = gacc[2][gate][b], ov = gacc[3][gate][b];
        float cm = c_s[gate][b] * (1.f - d_s[b]);
        float cn = sigm(fv) * cm + sigm(iv) * tanhf(gv);
        float hn = sigm(ov) * tanhf(cn);
        c_s[gate][b] = cn;
        last_h = hn; last_c = cn;
        __stcg(&hw[(j0 + gate)*32 + b], hn);
        g_hs[(t*32 + b)*128 + j0 + gate] = hn;
        grid_barrier();
    }
    out[OFF_HT + b*128 + j0 + gate] = last_h;
    out[OFF_CT + b*128 + j0 + gate] = last_c;
}

// ---------------- heads: logits + value, warp-per-row (coalesced hs reads) ----------------
// 128 blocks x 256 threads = 8 warps/block; warp w of block handles row n = blk*32 + ...
// Each warp: lanes cover k in 4 chunks of 32; per-lane partials for 6 logits + value;
// butterfly reduce; lanes 0..6 write.
__global__ void heads_kernel(const float* __restrict__ Wa, const float* __restrict__ ba,
                             const float* __restrict__ Wc, const float* __restrict__ bc,
                             float* __restrict__ out) {
    __shared__ float wa_s[AA*HH];
    __shared__ float wc_s[HH];
    int tid = threadIdx.x;
    for (int i = tid; i < AA*HH; i += blockDim.x) wa_s[i] = Wa[i];
    for (int i = tid; i < HH; i += blockDim.x) wc_s[i] = Wc[i];
    __syncthreads();

    int warp = tid >> 5, lane = tid & 31;
    int n = blockIdx.x * 8 + warp;            // 512 blocks would overshoot; grid is 512
    if (n >= NN) return;

    float la[AA];
    #pragma unroll
    for (int a = 0; a < AA; a++) la[a] = 0.f;
    float v = 0.f;
    #pragma unroll
    for (int kc = 0; kc < 4; kc++) {
        int k = kc*32 + lane;
        float hv = g_hs[n*HH + k];            // coalesced across the warp
        #pragma unroll
        for (int a = 0; a < AA; a++) la[a] += wa_s[a*HH + k] * hv;
        v += wc_s[k] * hv;
    }
    #pragma unroll
    for (int off = 16; off > 0; off >>= 1) {
        #pragma unroll
        for (int a = 0; a < AA; a++) la[a] += __shfl_xor_sync(0xffffffffu, la[a], off);
        v += __shfl_xor_sync(0xffffffffu, v, off);
    }
    if (lane < AA) out[OFF_LOGITS + n*AA + lane] = la[lane] + ba[lane];
    if (lane == AA) out[OFF_VALUE + n] = v + bc[0];
}

// ---------------- launcher ----------------
extern "C" void kernel_launch(void* const* d_in, const int* in_sizes, int n_in,
                              void* d_out, int out_size) {
    const float* x    = (const float*)d_in[0];
    const float* done = (const float*)d_in[1];
    const float* h0   = (const float*)d_in[2];
    const float* c0   = (const float*)d_in[3];
    const float* W1   = (const float*)d_in[4];
    const float* b1   = (const float*)d_in[5];
    const float* W2   = (const float*)d_in[6];
    const float* b2   = (const float*)d_in[7];
    const float* W3   = (const float*)d_in[8];
    const float* b3   = (const float*)d_in[9];
    const float* Wfc  = (const float*)d_in[10];
    const float* bfc  = (const float*)d_in[11];
    const float* W_ih = (const float*)d_in[12];
    const float* W_hh = (const float*)d_in[13];
    const float* b_ih = (const float*)d_in[14];
    const float* b_hh = (const float*)d_in[15];
    const float* Wa   = (const float*)d_in[16];
    const float* ba   = (const float*)d_in[17];
    const float* Wc   = (const float*)d_in[18];
    const float* bc   = (const float*)d_in[19];
    float* out = (float*)d_out;

    float* z3 = nullptr, *hid = nullptr, *gx = nullptr;
    cudaGetSymbolAddress((void**)&z3,  g_z3);
    cudaGetSymbolAddress((void**)&hid, g_hidden);
    cudaGetSymbolAddress((void**)&gx,  g_gx);

    prep_kernel<<<64, 256>>>(W1, W2, W3);
    conv1_kernel<<<NN, 320>>>(x, b1);
    conv2_kernel<<<NN, 160>>>(b2);
    conv3_kernel<<<NN, 128>>>(b3);
    gemm_nt_kernel<<<dim3(8, 64), 256>>>(z3,  Wfc,  bfc,  hid, NN, 512, 3136, 1);
    gemm_nt_kernel<<<dim3(8, 64), 256>>>(hid, W_ih, b_ih, gx,  NN, 512, 512,  0);
    lstm_kernel<<<NB_LSTM, 128>>>(gx, done, h0, c0, W_hh, b_hh, out);
    heads_kernel<<<512, 256>>>(Wa, ba, Wc, bc, out);
}

// round 7
// speedup vs baseline: 1.2022x; 1.2022x over previous
#include <cuda_runtime.h>
#include <math.h>
#include <stdint.h>

// ---------------- problem constants ----------------
#define TT 128
#define BB 32
#define NN (TT*BB)      // 4096
#define HH 128
#define AA 6

// output layout: logits (4096*6) | value (4096) | hT (32*128) | cT (32*128)
#define OFF_LOGITS 0
#define OFF_VALUE  24576
#define OFF_HT     28672
#define OFF_CT     32768

// ---------------- device scratch ----------------
__device__ float g_z1[NN*32*20*20];     // conv1 out
__device__ float g_z2[NN*64*9*9];       // conv2 out
__device__ float g_z3[NN*3136];         // conv3 out, flattened torch order
__device__ float g_hidden[NN*512];      // fc out
__device__ float g_gx[NN*512];          // gates_x
__device__ float g_hs[NN*HH];           // per-step hidden outputs
__device__ float g_hA[BB*HH];           // double-buffered h, layout [j*32+b]
__device__ float g_hB[BB*HH];
__device__ float g_w1t[64*32];          // [ky*8+kx][oc], pre-scaled by 1/255
__device__ float g_w2t[512*64];         // [ic*16+ky*4+kx][oc]
__device__ float g_w3t[576*64];         // [ic*9+ky*3+kx][oc]

__device__ int g_bar_cnt;               // zero-init; returns to 0 after each barrier
__device__ volatile unsigned g_bar_gen; // monotonic; equality-compared -> replay safe

__device__ __forceinline__ float sigm(float x) { return 1.f / (1.f + expf(-x)); }

// ---------------- cp.async helpers ----------------
__device__ __forceinline__ void cp16(uint32_t saddr, const void* gptr) {
    asm volatile("cp.async.cg.shared.global [%0], [%1], 16;" :: "r"(saddr), "l"(gptr));
}
#define CP_COMMIT() asm volatile("cp.async.commit_group;")
#define CP_WAIT(n)  asm volatile("cp.async.wait_group %0;" :: "n"(n))
__device__ __forceinline__ uint32_t s2u(const void* p) {
    return (uint32_t)__cvta_generic_to_shared(p);
}

// ---------------- weight pre-transpose ----------------
__global__ void prep_kernel(const float* __restrict__ W1,
                            const float* __restrict__ W2,
                            const float* __restrict__ W3) {
    int i = blockIdx.x * blockDim.x + threadIdx.x;
    int stride = gridDim.x * blockDim.x;
    for (int t = i; t < 2048; t += stride) {          // W1: (32,1,8,8), fold /255
        int oc = t / 64, p = t % 64;
        g_w1t[p*32 + oc] = W1[oc*64 + p] * (1.f/255.f);
    }
    for (int t = i; t < 32768; t += stride) {         // W2: (64,32,4,4)
        int oc = t / 512, p = t % 512;
        g_w2t[p*64 + oc] = W2[oc*512 + p];
    }
    for (int t = i; t < 36864; t += stride) {         // W3: (64,64,3,3)
        int oc = t / 576, p = t % 576;
        g_w3t[p*64 + oc] = W3[oc*576 + p];
    }
}

// ---------------- conv1: (1,84,84) -> (32,20,20), k8 s4, relu ----------------
// 4096 blocks x 320 threads. thread = (ocg 0..7, oy 0..19, oxhalf 0..1), 4 oc x 10 ox.
// x/255 folded into pre-scaled weights. Raw img staged via cp.async.
__global__ void __launch_bounds__(320, 2)
conv1_kernel(const float* __restrict__ x, const float* __restrict__ b1) {
    __shared__ __align__(16) float img[84*84];
    __shared__ __align__(16) float w_s[64*32];
    int n = blockIdx.x, tid = threadIdx.x;

    uint32_t img_s = s2u(img), ws_s = s2u(w_s);
    for (int i = tid; i < 1764; i += 320) cp16(img_s + i*16, x + n*7056 + i*4);
    for (int i = tid; i < 512;  i += 320) cp16(ws_s + i*16, g_w1t + i*4);
    CP_COMMIT();
    CP_WAIT(0);
    __syncthreads();

    int ocg = tid & 7;
    int oy  = (tid >> 3) % 20;
    int oxh = tid / 160;
    int oc0 = ocg * 4;

    float acc[4][10];
    #pragma unroll
    for (int m = 0; m < 4; m++)
        #pragma unroll
        for (int o = 0; o < 10; o++) acc[m][o] = 0.f;

    #pragma unroll
    for (int ky = 0; ky < 8; ky++) {
        const float* row = &img[(oy*4 + ky)*84 + oxh*40];
        float in_r[44];
        #pragma unroll
        for (int c = 0; c < 11; c++) {
            float4 v = *(const float4*)&row[c*4];
            in_r[c*4+0] = v.x; in_r[c*4+1] = v.y; in_r[c*4+2] = v.z; in_r[c*4+3] = v.w;
        }
        #pragma unroll
        for (int kx = 0; kx < 8; kx++) {
            float4 w4 = *(const float4*)&w_s[(ky*8 + kx)*32 + oc0];
            #pragma unroll
            for (int ox = 0; ox < 10; ox++) {
                float iv = in_r[ox*4 + kx];
                acc[0][ox] += w4.x * iv;
                acc[1][ox] += w4.y * iv;
                acc[2][ox] += w4.z * iv;
                acc[3][ox] += w4.w * iv;
            }
        }
    }
    #pragma unroll
    for (int m = 0; m < 4; m++) {
        int oc = oc0 + m;
        float bv = b1[oc];
        #pragma unroll
        for (int ox = 0; ox < 10; ox++) {
            float v = acc[m][ox] + bv;
            g_z1[((n*32 + oc)*20 + oy)*20 + oxh*10 + ox] = v > 0.f ? v : 0.f;
        }
    }
}

// ---------------- conv2: (32,20,20) -> (64,9,9), k4 s2, relu ----------------
// 4096 blocks x 160 threads (144 compute). ic-chunks of 4, 8 chunks, cp.async dbuf.
#define C2_INF 1600   // 4 ic * 400
#define C2_WF  4096   // 4 ic * 16 * 64
__global__ void __launch_bounds__(160, 4)
conv2_kernel(const float* __restrict__ b2) {
    __shared__ __align__(16) float in_s[2][C2_INF];
    __shared__ __align__(16) float w_s[2][C2_WF];
    int n = blockIdx.x, tid = threadIdx.x;
    int ocg = tid & 15;
    int oy  = tid >> 4;                 // valid when tid < 144
    int oc0 = ocg * 4;

    float acc[4][9];
    #pragma unroll
    for (int m = 0; m < 4; m++)
        #pragma unroll
        for (int o = 0; o < 9; o++) acc[m][o] = 0.f;

    // prologue: stage chunk 0 into buf 0
    {
        uint32_t si = s2u(in_s[0]), sw = s2u(w_s[0]);
        for (int i = tid; i < 400;  i += 160) cp16(si + i*16, g_z1 + n*12800 + i*4);
        for (int i = tid; i < 1024; i += 160) cp16(sw + i*16, g_w2t + i*4);
        CP_COMMIT();
    }

    for (int cc = 0; cc < 8; cc++) {
        if (cc + 1 < 8) {
            int nb = (cc + 1) & 1;
            uint32_t si = s2u(in_s[nb]), sw = s2u(w_s[nb]);
            for (int i = tid; i < 400;  i += 160)
                cp16(si + i*16, g_z1 + n*12800 + (cc+1)*1600 + i*4);
            for (int i = tid; i < 1024; i += 160)
                cp16(sw + i*16, g_w2t + (cc+1)*4096 + i*4);
            CP_COMMIT();
            CP_WAIT(1);
        } else {
            CP_WAIT(0);
        }
        __syncthreads();
        int cb = cc & 1;
        if (tid < 144) {
            #pragma unroll
            for (int ic = 0; ic < 4; ic++) {
                #pragma unroll
                for (int ky = 0; ky < 4; ky++) {
                    const float* row = &in_s[cb][ic*400 + (oy*2 + ky)*20];
                    float in_r[20];
                    #pragma unroll
                    for (int c = 0; c < 5; c++) {
                        float4 v = *(const float4*)&row[c*4];
                        in_r[c*4+0] = v.x; in_r[c*4+1] = v.y; in_r[c*4+2] = v.z; in_r[c*4+3] = v.w;
                    }
                    #pragma unroll
                    for (int kx = 0; kx < 4; kx++) {
                        float4 w4 = *(const float4*)&w_s[cb][(ic*16 + ky*4 + kx)*64 + oc0];
                        #pragma unroll
                        for (int ox = 0; ox < 9; ox++) {
                            float iv = in_r[ox*2 + kx];
                            acc[0][ox] += w4.x * iv;
                            acc[1][ox] += w4.y * iv;
                            acc[2][ox] += w4.z * iv;
                            acc[3][ox] += w4.w * iv;
                        }
                    }
                }
            }
        }
        __syncthreads();
    }
    if (tid < 144) {
        #pragma unroll
        for (int m = 0; m < 4; m++) {
            int oc = oc0 + m;
            float bv = b2[oc];
            #pragma unroll
            for (int ox = 0; ox < 9; ox++) {
                float v = acc[m][ox] + bv;
                g_z2[((n*64 + oc)*9 + oy)*9 + ox] = v > 0.f ? v : 0.f;
            }
        }
    }
}

// ---------------- conv3: (64,9,9) -> (64,7,7), k3 s1, relu ----------------
// 4096 blocks x 128 threads (112 compute). ic-chunks of 8, 8 chunks, cp.async dbuf.
// input tile unpadded (rows of 9) -> straight contiguous copy from g_z2.
#define C3_INF 648    // 8 ic * 81
#define C3_WF  4608   // 8 ic * 9 * 64
__global__ void __launch_bounds__(128, 5)
conv3_kernel(const float* __restrict__ b3) {
    __shared__ __align__(16) float in_s[2][C3_INF];
    __shared__ __align__(16) float w_s[2][C3_WF];
    int n = blockIdx.x, tid = threadIdx.x;
    int ocg = tid & 15;
    int oy  = tid >> 4;                 // valid when tid < 112
    int oc0 = ocg * 4;

    float acc[4][7];
    #pragma unroll
    for (int m = 0; m < 4; m++)
        #pragma unroll
        for (int o = 0; o < 7; o++) acc[m][o] = 0.f;

    {
        uint32_t si = s2u(in_s[0]), sw = s2u(w_s[0]);
        for (int i = tid; i < 162;  i += 128) cp16(si + i*16, g_z2 + n*5184 + i*4);
        for (int i = tid; i < 1152; i += 128) cp16(sw + i*16, g_w3t + i*4);
        CP_COMMIT();
    }

    for (int cc = 0; cc < 8; cc++) {
        if (cc + 1 < 8) {
            int nb = (cc + 1) & 1;
            uint32_t si = s2u(in_s[nb]), sw = s2u(w_s[nb]);
            for (int i = tid; i < 162;  i += 128)
                cp16(si + i*16, g_z2 + n*5184 + (cc+1)*648 + i*4);
            for (int i = tid; i < 1152; i += 128)
                cp16(sw + i*16, g_w3t + (cc+1)*4608 + i*4);
            CP_COMMIT();
            CP_WAIT(1);
        } else {
            CP_WAIT(0);
        }
        __syncthreads();
        int cb = cc & 1;
        if (tid < 112) {
            #pragma unroll
            for (int ic = 0; ic < 8; ic++) {
                #pragma unroll
                for (int ky = 0; ky < 3; ky++) {
                    const float* row = &in_s[cb][ic*81 + (oy + ky)*9];
                    float in_r[9];
                    #pragma unroll
                    for (int c = 0; c < 9; c++) in_r[c] = row[c];
                    #pragma unroll
                    for (int kx = 0; kx < 3; kx++) {
                        float4 w4 = *(const float4*)&w_s[cb][(ic*9 + ky*3 + kx)*64 + oc0];
                        #pragma unroll
                        for (int ox = 0; ox < 7; ox++) {
                            float iv = in_r[ox + kx];
                            acc[0][ox] += w4.x * iv;
                            acc[1][ox] += w4.y * iv;
                            acc[2][ox] += w4.z * iv;
                            acc[3][ox] += w4.w * iv;
                        }
                    }
                }
            }
        }
        __syncthreads();
    }
    if (tid < 112) {
        #pragma unroll
        for (int m = 0; m < 4; m++) {
            int oc = oc0 + m;
            float bv = b3[oc];
            #pragma unroll
            for (int ox = 0; ox < 7; ox++) {
                float v = acc[m][ox] + bv;
                g_z3[n*3136 + oc*49 + oy*7 + ox] = v > 0.f ? v : 0.f;
            }
        }
    }
}

// ---------------- NT GEMM: C[M,N] = act(A[M,K] @ B[N,K]^T + bias[N]) ----------------
// 128x64 tile, 256 threads, 8x4 per thread, k-tile 16, register double-buffered loads.
__global__ void __launch_bounds__(256)
gemm_nt_kernel(const float* __restrict__ A, const float* __restrict__ B,
               const float* __restrict__ bias, float* __restrict__ C,
               int M, int N, int K, int relu) {
    __shared__ float As[16][128];
    __shared__ float Bs[16][64];
    int m0 = blockIdx.y * 128, n0 = blockIdx.x * 64;
    int tid = threadIdx.x;
    int tm = tid >> 4, tn = tid & 15;       // rows tm*8.., cols tn*4..
    int sr = tid >> 2, sc = (tid & 3) * 4;  // staging: row, k-offset

    float acc[8][4];
    #pragma unroll
    for (int i = 0; i < 8; i++)
        #pragma unroll
        for (int j = 0; j < 4; j++) acc[i][j] = 0.f;

    const float* Ap0 = A + (m0 + sr) * K + sc;        // rows sr and sr+64
    const float* Ap1 = A + (m0 + sr + 64) * K + sc;
    const float* Bp  = B + (n0 + sr) * K + sc;        // sr < 64 covers all B rows

    float4 a_f0 = *(const float4*)Ap0;
    float4 a_f1 = *(const float4*)Ap1;
    float4 b_f  = *(const float4*)Bp;

    for (int k0 = 0; k0 < K; k0 += 16) {
        As[sc+0][sr] = a_f0.x; As[sc+1][sr] = a_f0.y; As[sc+2][sr] = a_f0.z; As[sc+3][sr] = a_f0.w;
        As[sc+0][sr+64] = a_f1.x; As[sc+1][sr+64] = a_f1.y; As[sc+2][sr+64] = a_f1.z; As[sc+3][sr+64] = a_f1.w;
        Bs[sc+0][sr] = b_f.x; Bs[sc+1][sr] = b_f.y; Bs[sc+2][sr] = b_f.z; Bs[sc+3][sr] = b_f.w;
        __syncthreads();
        if (k0 + 16 < K) {
            a_f0 = *(const float4*)(Ap0 + k0 + 16);
            a_f1 = *(const float4*)(Ap1 + k0 + 16);
            b_f  = *(const float4*)(Bp  + k0 + 16);
        }
        #pragma unroll
        for (int k = 0; k < 16; k++) {
            float4 a4a = *(const float4*)&As[k][tm*8];
            float4 a4b = *(const float4*)&As[k][tm*8 + 4];
            float4 b4  = *(const float4*)&Bs[k][tn*4];
            float am[8] = {a4a.x, a4a.y, a4a.z, a4a.w, a4b.x, a4b.y, a4b.z, a4b.w};
            float bn[4] = {b4.x, b4.y, b4.z, b4.w};
            #pragma unroll
            for (int i = 0; i < 8; i++)
                #pragma unroll
                for (int j = 0; j < 4; j++) acc[i][j] += am[i] * bn[j];
        }
        __syncthreads();
    }
    float bsv[4];
    #pragma unroll
    for (int j = 0; j < 4; j++) bsv[j] = bias[n0 + tn*4 + j];
    #pragma unroll
    for (int i = 0; i < 8; i++) {
        int m = m0 + tm*8 + i;
        float4 v;
        v.x = acc[i][0] + bsv[0]; v.y = acc[i][1] + bsv[1];
        v.z = acc[i][2] + bsv[2]; v.w = acc[i][3] + bsv[3];
        if (relu) {
            v.x = v.x > 0.f ? v.x : 0.f; v.y = v.y > 0.f ? v.y : 0.f;
            v.z = v.z > 0.f ? v.z : 0.f; v.w = v.w > 0.f ? v.w : 0.f;
        }
        *(float4*)&C[m*N + n0 + tn*4] = v;
    }
}

// ---------------- persistent LSTM scan ----------------
#define NB_LSTM 32
__device__ __forceinline__ void grid_barrier() {
    __threadfence();
    __syncthreads();
    if (threadIdx.x == 0) {
        unsigned gen = g_bar_gen;
        if (atomicAdd(&g_bar_cnt, 1) == NB_LSTM - 1) {
            atomicExch(&g_bar_cnt, 0);
            __threadfence();
            g_bar_gen = gen + 1;
        } else {
            while (g_bar_gen == gen) { __nanosleep(40); }
        }
        __threadfence();
    }
    __syncthreads();
}

// 32 blocks x 128 threads. Block q owns hidden units j in [q*4, q*4+4).
__global__ void __launch_bounds__(128, 1)
lstm_kernel(const float* __restrict__ gx, const float* __restrict__ done,
            const float* __restrict__ h0, const float* __restrict__ c0,
            const float* __restrict__ W_hh, const float* __restrict__ b_hh,
            float* __restrict__ out) {
    __shared__ float w_s[4][128][4];   // [gate][k][jl]
    __shared__ float h_sm[128*32];     // [k*32+b], masked h
    __shared__ float gacc[4][4][32];   // [gate][jl][b]
    __shared__ float c_s[4][32];
    __shared__ float d_s[32];
    __shared__ float bb_s[4][4];

    int q = blockIdx.x, tid = threadIdx.x;
    int j0 = q * 4;
    int gate = tid >> 5;               // also serves as jl in the epilogue
    int b = tid & 31;

    for (int i = tid; i < 2048; i += 128) {
        int jl = i & 3, k = (i >> 2) & 127, g = i >> 9;
        w_s[g][k][jl] = W_hh[(g*128 + j0 + jl)*128 + k];
    }
    if (tid < 16) bb_s[tid >> 2][tid & 3] = b_hh[(tid >> 2)*128 + j0 + (tid & 3)];
    c_s[gate][b] = c0[b*128 + j0 + gate];
    __stcg(&g_hA[(j0 + gate)*32 + b], h0[b*128 + j0 + gate]);
    grid_barrier();

    float last_h = 0.f, last_c = 0.f;
    for (int t = 0; t < TT; t++) {
        const float* hr = (t & 1) ? g_hB : g_hA;
        float*       hw = (t & 1) ? g_hA : g_hB;
        if (tid < 32) d_s[tid] = done[t*32 + tid];
        __syncthreads();
        for (int i = tid; i < 4096; i += 128)
            h_sm[i] = __ldcg(&hr[i]) * (1.f - d_s[i & 31]);
        __syncthreads();

        const float* gxr = &gx[(t*32 + b)*512 + gate*128 + j0];
        float a0 = gxr[0] + bb_s[gate][0];
        float a1 = gxr[1] + bb_s[gate][1];
        float a2 = gxr[2] + bb_s[gate][2];
        float a3 = gxr[3] + bb_s[gate][3];
        #pragma unroll 8
        for (int k = 0; k < 128; k++) {
            float hv = h_sm[k*32 + b];
            float4 w4 = *(const float4*)&w_s[gate][k][0];
            a0 += w4.x * hv; a1 += w4.y * hv; a2 += w4.z * hv; a3 += w4.w * hv;
        }
        gacc[gate][0][b] = a0; gacc[gate][1][b] = a1;
        gacc[gate][2][b] = a2; gacc[gate][3][b] = a3;
        __syncthreads();

        float iv = gacc[0][gate][b], fv = gacc[1][gate][b];
        float gv = gacc[2][gate][b], ov = gacc[3][gate][b];
        float cm = c_s[gate][b] * (1.f - d_s[b]);
        float cn = sigm(fv) * cm + sigm(iv) * tanhf(gv);
        float hn = sigm(ov) * tanhf(cn);
        c_s[gate][b] = cn;
        last_h = hn; last_c = cn;
        __stcg(&hw[(j0 + gate)*32 + b], hn);
        g_hs[(t*32 + b)*128 + j0 + gate] = hn;
        grid_barrier();
    }
    out[OFF_HT + b*128 + j0 + gate] = last_h;
    out[OFF_CT + b*128 + j0 + gate] = last_c;
}

// ---------------- heads: logits + value, warp-per-row ----------------
__global__ void heads_kernel(const float* __restrict__ Wa, const float* __restrict__ ba,
                             const float* __restrict__ Wc, const float* __restrict__ bc,
                             float* __restrict__ out) {
    __shared__ float wa_s[AA*HH];
    __shared__ float wc_s[HH];
    int tid = threadIdx.x;
    for (int i = tid; i < AA*HH; i += blockDim.x) wa_s[i] = Wa[i];
    for (int i = tid; i < HH; i += blockDim.x) wc_s[i] = Wc[i];
    __syncthreads();

    int warp = tid >> 5, lane = tid & 31;
    int n = blockIdx.x * 8 + warp;
    if (n >= NN) return;

    float la[AA];
    #pragma unroll
    for (int a = 0; a < AA; a++) la[a] = 0.f;
    float v = 0.f;
    #pragma unroll
    for (int kc = 0; kc < 4; kc++) {
        int k = kc*32 + lane;
        float hv = g_hs[n*HH + k];
        #pragma unroll
        for (int a = 0; a < AA; a++) la[a] += wa_s[a*HH + k] * hv;
        v += wc_s[k] * hv;
    }
    #pragma unroll
    for (int off = 16; off > 0; off >>= 1) {
        #pragma unroll
        for (int a = 0; a < AA; a++) la[a] += __shfl_xor_sync(0xffffffffu, la[a], off);
        v += __shfl_xor_sync(0xffffffffu, v, off);
    }
    if (lane < AA) out[OFF_LOGITS + n*AA + lane] = la[lane] + ba[lane];
    if (lane == AA) out[OFF_VALUE + n] = v + bc[0];
}

// ---------------- launcher ----------------
extern "C" void kernel_launch(void* const* d_in, const int* in_sizes, int n_in,
                              void* d_out, int out_size) {
    const float* x    = (const float*)d_in[0];
    const float* done = (const float*)d_in[1];
    const float* h0   = (const float*)d_in[2];
    const float* c0   = (const float*)d_in[3];
    const float* W1   = (const float*)d_in[4];
    const float* b1   = (const float*)d_in[5];
    const float* W2   = (const float*)d_in[6];
    const float* b2   = (const float*)d_in[7];
    const float* W3   = (const float*)d_in[8];
    const float* b3   = (const float*)d_in[9];
    const float* Wfc  = (const float*)d_in[10];
    const float* bfc  = (const float*)d_in[11];
    const float* W_ih = (const float*)d_in[12];
    const float* W_hh = (const float*)d_in[13];
    const float* b_ih = (const float*)d_in[14];
    const float* b_hh = (const float*)d_in[15];
    const float* Wa   = (const float*)d_in[16];
    const float* ba   = (const float*)d_in[17];
    const float* Wc   = (const float*)d_in[18];
    const float* bc   = (const float*)d_in[19];
    float* out = (float*)d_out;

    float* z3 = nullptr, *hid = nullptr, *gx = nullptr;
    cudaGetSymbolAddress((void**)&z3,  g_z3);
    cudaGetSymbolAddress((void**)&hid, g_hidden);
    cudaGetSymbolAddress((void**)&gx,  g_gx);

    prep_kernel<<<64, 256>>>(W1, W2, W3);
    conv1_kernel<<<NN, 320>>>(x, b1);
    conv2_kernel<<<NN, 160>>>(b2);
    conv3_kernel<<<NN, 128>>>(b3);
    gemm_nt_kernel<<<dim3(8, 32), 256>>>(z3,  Wfc,  bfc,  hid, NN, 512, 3136, 1);
    gemm_nt_kernel<<<dim3(8, 32), 256>>>(hid, W_ih, b_ih, gx,  NN, 512, 512,  0);
    lstm_kernel<<<NB_LSTM, 128>>>(gx, done, h0, c0, W_hh, b_hh, out);
    heads_kernel<<<512, 256>>>(Wa, ba, Wc, bc, out);
}

// round 8
// speedup vs baseline: 1.3082x; 1.0882x over previous
#include <cuda_runtime.h>
#include <math.h>
#include <stdint.h>

// ---------------- problem constants ----------------
#define TT 128
#define BB 32
#define NN (TT*BB)      // 4096
#define HH 128
#define AA 6

// output layout: logits (4096*6) | value (4096) | hT (32*128) | cT (32*128)
#define OFF_LOGITS 0
#define OFF_VALUE  24576
#define OFF_HT     28672
#define OFF_CT     32768

// ---------------- device scratch ----------------
__device__ float g_z1[NN*32*20*20];     // conv1 out
__device__ float g_z2[NN*64*9*9];       // conv2 out
__device__ float g_z3[NN*3136];         // conv3 out, flattened torch order
__device__ float g_hidden[NN*512];      // fc out
__device__ float g_gx[NN*512];          // gates_x
__device__ float g_hs[NN*HH];           // per-step hidden outputs
__device__ float g_hA[BB*HH];           // double-buffered h, layout [j*32+b]
__device__ float g_hB[BB*HH];
__device__ float g_w1t[64*32];          // [ky*8+kx][oc], pre-scaled by 1/255
__device__ float g_w2t[512*64];         // [ic*16+ky*4+kx][oc]
__device__ float g_w3t[576*64];         // [ic*9+ky*3+kx][oc]

__device__ int g_bar_cnt;               // zero-init; returns to 0 after each barrier
__device__ volatile unsigned g_bar_gen; // monotonic; equality-compared -> replay safe

__device__ __forceinline__ float sigm(float x) { return 1.f / (1.f + expf(-x)); }

// ---------------- cp.async helpers ----------------
__device__ __forceinline__ void cp16(uint32_t saddr, const void* gptr) {
    asm volatile("cp.async.cg.shared.global [%0], [%1], 16;" :: "r"(saddr), "l"(gptr));
}
#define CP_COMMIT() asm volatile("cp.async.commit_group;")
#define CP_WAIT(n)  asm volatile("cp.async.wait_group %0;" :: "n"(n))
__device__ __forceinline__ uint32_t s2u(const void* p) {
    return (uint32_t)__cvta_generic_to_shared(p);
}

// ---------------- tf32 mma helpers ----------------
__device__ __forceinline__ uint32_t f2tf(float f) {
    uint32_t u;
    asm("cvt.rna.tf32.f32 %0, %1;" : "=r"(u) : "f"(f));
    return u;
}
__device__ __forceinline__ void mma_tf32(float* d, const uint32_t* a, const uint32_t* b) {
    asm volatile(
        "mma.sync.aligned.m16n8k8.row.col.f32.tf32.tf32.f32 "
        "{%0,%1,%2,%3}, {%4,%5,%6,%7}, {%8,%9}, {%0,%1,%2,%3};\n"
        : "+f"(d[0]), "+f"(d[1]), "+f"(d[2]), "+f"(d[3])
        : "r"(a[0]), "r"(a[1]), "r"(a[2]), "r"(a[3]), "r"(b[0]), "r"(b[1]));
}

// ---------------- weight pre-transpose ----------------
__global__ void prep_kernel(const float* __restrict__ W1,
                            const float* __restrict__ W2,
                            const float* __restrict__ W3) {
    int i = blockIdx.x * blockDim.x + threadIdx.x;
    int stride = gridDim.x * blockDim.x;
    for (int t = i; t < 2048; t += stride) {          // W1: (32,1,8,8), fold /255
        int oc = t / 64, p = t % 64;
        g_w1t[p*32 + oc] = W1[oc*64 + p] * (1.f/255.f);
    }
    for (int t = i; t < 32768; t += stride) {         // W2: (64,32,4,4)
        int oc = t / 512, p = t % 512;
        g_w2t[p*64 + oc] = W2[oc*512 + p];
    }
    for (int t = i; t < 36864; t += stride) {         // W3: (64,64,3,3)
        int oc = t / 576, p = t % 576;
        g_w3t[p*64 + oc] = W3[oc*576 + p];
    }
}

// ---------------- conv1: (1,84,84) -> (32,20,20), k8 s4, relu ----------------
__global__ void __launch_bounds__(320, 2)
conv1_kernel(const float* __restrict__ x, const float* __restrict__ b1) {
    __shared__ __align__(16) float img[84*84];
    __shared__ __align__(16) float w_s[64*32];
    int n = blockIdx.x, tid = threadIdx.x;

    uint32_t img_s = s2u(img), ws_s = s2u(w_s);
    for (int i = tid; i < 1764; i += 320) cp16(img_s + i*16, x + n*7056 + i*4);
    for (int i = tid; i < 512;  i += 320) cp16(ws_s + i*16, g_w1t + i*4);
    CP_COMMIT();
    CP_WAIT(0);
    __syncthreads();

    int ocg = tid & 7;
    int oy  = (tid >> 3) % 20;
    int oxh = tid / 160;
    int oc0 = ocg * 4;

    float acc[4][10];
    #pragma unroll
    for (int m = 0; m < 4; m++)
        #pragma unroll
        for (int o = 0; o < 10; o++) acc[m][o] = 0.f;

    #pragma unroll
    for (int ky = 0; ky < 8; ky++) {
        const float* row = &img[(oy*4 + ky)*84 + oxh*40];
        float in_r[44];
        #pragma unroll
        for (int c = 0; c < 11; c++) {
            float4 v = *(const float4*)&row[c*4];
            in_r[c*4+0] = v.x; in_r[c*4+1] = v.y; in_r[c*4+2] = v.z; in_r[c*4+3] = v.w;
        }
        #pragma unroll
        for (int kx = 0; kx < 8; kx++) {
            float4 w4 = *(const float4*)&w_s[(ky*8 + kx)*32 + oc0];
            #pragma unroll
            for (int ox = 0; ox < 10; ox++) {
                float iv = in_r[ox*4 + kx];
                acc[0][ox] += w4.x * iv;
                acc[1][ox] += w4.y * iv;
                acc[2][ox] += w4.z * iv;
                acc[3][ox] += w4.w * iv;
            }
        }
    }
    #pragma unroll
    for (int m = 0; m < 4; m++) {
        int oc = oc0 + m;
        float bv = b1[oc];
        #pragma unroll
        for (int ox = 0; ox < 10; ox++) {
            float v = acc[m][ox] + bv;
            g_z1[((n*32 + oc)*20 + oy)*20 + oxh*10 + ox] = v > 0.f ? v : 0.f;
        }
    }
}

// ---------------- conv2: (32,20,20) -> (64,9,9), k4 s2, relu ----------------
#define C2_INF 1600   // 4 ic * 400
#define C2_WF  4096   // 4 ic * 16 * 64
__global__ void __launch_bounds__(160, 4)
conv2_kernel(const float* __restrict__ b2) {
    __shared__ __align__(16) float in_s[2][C2_INF];
    __shared__ __align__(16) float w_s[2][C2_WF];
    int n = blockIdx.x, tid = threadIdx.x;
    int ocg = tid & 15;
    int oy  = tid >> 4;                 // valid when tid < 144
    int oc0 = ocg * 4;

    float acc[4][9];
    #pragma unroll
    for (int m = 0; m < 4; m++)
        #pragma unroll
        for (int o = 0; o < 9; o++) acc[m][o] = 0.f;

    {
        uint32_t si = s2u(in_s[0]), sw = s2u(w_s[0]);
        for (int i = tid; i < 400;  i += 160) cp16(si + i*16, g_z1 + n*12800 + i*4);
        for (int i = tid; i < 1024; i += 160) cp16(sw + i*16, g_w2t + i*4);
        CP_COMMIT();
    }

    for (int cc = 0; cc < 8; cc++) {
        if (cc + 1 < 8) {
            int nb = (cc + 1) & 1;
            uint32_t si = s2u(in_s[nb]), sw = s2u(w_s[nb]);
            for (int i = tid; i < 400;  i += 160)
                cp16(si + i*16, g_z1 + n*12800 + (cc+1)*1600 + i*4);
            for (int i = tid; i < 1024; i += 160)
                cp16(sw + i*16, g_w2t + (cc+1)*4096 + i*4);
            CP_COMMIT();
            CP_WAIT(1);
        } else {
            CP_WAIT(0);
        }
        __syncthreads();
        int cb = cc & 1;
        if (tid < 144) {
            #pragma unroll
            for (int ic = 0; ic < 4; ic++) {
                #pragma unroll
                for (int ky = 0; ky < 4; ky++) {
                    const float* row = &in_s[cb][ic*400 + (oy*2 + ky)*20];
                    float in_r[20];
                    #pragma unroll
                    for (int c = 0; c < 5; c++) {
                        float4 v = *(const float4*)&row[c*4];
                        in_r[c*4+0] = v.x; in_r[c*4+1] = v.y; in_r[c*4+2] = v.z; in_r[c*4+3] = v.w;
                    }
                    #pragma unroll
                    for (int kx = 0; kx < 4; kx++) {
                        float4 w4 = *(const float4*)&w_s[cb][(ic*16 + ky*4 + kx)*64 + oc0];
                        #pragma unroll
                        for (int ox = 0; ox < 9; ox++) {
                            float iv = in_r[ox*2 + kx];
                            acc[0][ox] += w4.x * iv;
                            acc[1][ox] += w4.y * iv;
                            acc[2][ox] += w4.z * iv;
                            acc[3][ox] += w4.w * iv;
                        }
                    }
                }
            }
        }
        __syncthreads();
    }
    if (tid < 144) {
        #pragma unroll
        for (int m = 0; m < 4; m++) {
            int oc = oc0 + m;
            float bv = b2[oc];
            #pragma unroll
            for (int ox = 0; ox < 9; ox++) {
                float v = acc[m][ox] + bv;
                g_z2[((n*64 + oc)*9 + oy)*9 + ox] = v > 0.f ? v : 0.f;
            }
        }
    }
}

// ---------------- conv3: (64,9,9) -> (64,7,7), k3 s1, relu ----------------
#define C3_INF 648    // 8 ic * 81
#define C3_WF  4608   // 8 ic * 9 * 64
__global__ void __launch_bounds__(128, 5)
conv3_kernel(const float* __restrict__ b3) {
    __shared__ __align__(16) float in_s[2][C3_INF];
    __shared__ __align__(16) float w_s[2][C3_WF];
    int n = blockIdx.x, tid = threadIdx.x;
    int ocg = tid & 15;
    int oy  = tid >> 4;                 // valid when tid < 112
    int oc0 = ocg * 4;

    float acc[4][7];
    #pragma unroll
    for (int m = 0; m < 4; m++)
        #pragma unroll
        for (int o = 0; o < 7; o++) acc[m][o] = 0.f;

    {
        uint32_t si = s2u(in_s[0]), sw = s2u(w_s[0]);
        for (int i = tid; i < 162;  i += 128) cp16(si + i*16, g_z2 + n*5184 + i*4);
        for (int i = tid; i < 1152; i += 128) cp16(sw + i*16, g_w3t + i*4);
        CP_COMMIT();
    }

    for (int cc = 0; cc < 8; cc++) {
        if (cc + 1 < 8) {
            int nb = (cc + 1) & 1;
            uint32_t si = s2u(in_s[nb]), sw = s2u(w_s[nb]);
            for (int i = tid; i < 162;  i += 128)
                cp16(si + i*16, g_z2 + n*5184 + (cc+1)*648 + i*4);
            for (int i = tid; i < 1152; i += 128)
                cp16(sw + i*16, g_w3t + (cc+1)*4608 + i*4);
            CP_COMMIT();
            CP_WAIT(1);
        } else {
            CP_WAIT(0);
        }
        __syncthreads();
        int cb = cc & 1;
        if (tid < 112) {
            #pragma unroll
            for (int ic = 0; ic < 8; ic++) {
                #pragma unroll
                for (int ky = 0; ky < 3; ky++) {
                    const float* row = &in_s[cb][ic*81 + (oy + ky)*9];
                    float in_r[9];
                    #pragma unroll
                    for (int c = 0; c < 9; c++) in_r[c] = row[c];
                    #pragma unroll
                    for (int kx = 0; kx < 3; kx++) {
                        float4 w4 = *(const float4*)&w_s[cb][(ic*9 + ky*3 + kx)*64 + oc0];
                        #pragma unroll
                        for (int ox = 0; ox < 7; ox++) {
                            float iv = in_r[ox + kx];
                            acc[0][ox] += w4.x * iv;
                            acc[1][ox] += w4.y * iv;
                            acc[2][ox] += w4.z * iv;
                            acc[3][ox] += w4.w * iv;
                        }
                    }
                }
            }
        }
        __syncthreads();
    }
    if (tid < 112) {
        #pragma unroll
        for (int m = 0; m < 4; m++) {
            int oc = oc0 + m;
            float bv = b3[oc];
            #pragma unroll
            for (int ox = 0; ox < 7; ox++) {
                float v = acc[m][ox] + bv;
                g_z3[n*3136 + oc*49 + oy*7 + ox] = v > 0.f ? v : 0.f;
            }
        }
    }
}

// ---------------- tf32 NT GEMM: C[M,N] = act(A[M,K] @ B[N,K]^T + bias[N]) ----------------
// 128x64 tile, 256 threads = 8 warps (4x2). Warp tile 32x32 = 2x4 mma m16n8k8 tiles.
// Smem rows padded (132/68) so fragment gathers are bank-conflict-free.
// Requires K % 16 == 0, M % 128 == 0, N % 64 == 0.
__global__ void __launch_bounds__(256)
gemm_tf32_nt_kernel(const float* __restrict__ A, const float* __restrict__ B,
                    const float* __restrict__ bias, float* __restrict__ C,
                    int M, int N, int K, int relu) {
    __shared__ float As[16][132];
    __shared__ float Bs[16][68];
    int m0 = blockIdx.y * 128, n0 = blockIdx.x * 64;
    int tid = threadIdx.x;
    int warp = tid >> 5, lane = tid & 31;
    int wm = warp >> 1, wn = warp & 1;      // warp tile: rows wm*32.., cols wn*32..
    int g = lane >> 2, t = lane & 3;        // groupID, threadID_in_group
    int sr = tid >> 2, sc = (tid & 3) * 4;  // staging: row (0..63), k-offset

    float acc[2][4][4];
    #pragma unroll
    for (int mi = 0; mi < 2; mi++)
        #pragma unroll
        for (int ni = 0; ni < 4; ni++)
            #pragma unroll
            for (int r = 0; r < 4; r++) acc[mi][ni][r] = 0.f;

    const float* Ap0 = A + (m0 + sr) * K + sc;        // rows sr and sr+64
    const float* Ap1 = A + (m0 + sr + 64) * K + sc;
    const float* Bp  = B + (n0 + sr) * K + sc;

    float4 a_f0 = *(const float4*)Ap0;
    float4 a_f1 = *(const float4*)Ap1;
    float4 b_f  = *(const float4*)Bp;

    for (int k0 = 0; k0 < K; k0 += 16) {
        As[sc+0][sr] = a_f0.x; As[sc+1][sr] = a_f0.y; As[sc+2][sr] = a_f0.z; As[sc+3][sr] = a_f0.w;
        As[sc+0][sr+64] = a_f1.x; As[sc+1][sr+64] = a_f1.y; As[sc+2][sr+64] = a_f1.z; As[sc+3][sr+64] = a_f1.w;
        Bs[sc+0][sr] = b_f.x; Bs[sc+1][sr] = b_f.y; Bs[sc+2][sr] = b_f.z; Bs[sc+3][sr] = b_f.w;
        __syncthreads();
        if (k0 + 16 < K) {
            a_f0 = *(const float4*)(Ap0 + k0 + 16);
            a_f1 = *(const float4*)(Ap1 + k0 + 16);
            b_f  = *(const float4*)(Bp  + k0 + 16);
        }
        #pragma unroll
        for (int kk = 0; kk < 16; kk += 8) {
            uint32_t af[2][4];
            #pragma unroll
            for (int mi = 0; mi < 2; mi++) {
                int m = wm*32 + mi*16;
                af[mi][0] = f2tf(As[kk + t    ][m + g    ]);
                af[mi][1] = f2tf(As[kk + t    ][m + g + 8]);
                af[mi][2] = f2tf(As[kk + t + 4][m + g    ]);
                af[mi][3] = f2tf(As[kk + t + 4][m + g + 8]);
            }
            uint32_t bf[4][2];
            #pragma unroll
            for (int ni = 0; ni < 4; ni++) {
                int nb = wn*32 + ni*8;
                bf[ni][0] = f2tf(Bs[kk + t    ][nb + g]);
                bf[ni][1] = f2tf(Bs[kk + t + 4][nb + g]);
            }
            #pragma unroll
            for (int mi = 0; mi < 2; mi++)
                #pragma unroll
                for (int ni = 0; ni < 4; ni++)
                    mma_tf32(acc[mi][ni], af[mi], bf[ni]);
        }
        __syncthreads();
    }

    #pragma unroll
    for (int mi = 0; mi < 2; mi++) {
        #pragma unroll
        for (int ni = 0; ni < 4; ni++) {
            int m = m0 + wm*32 + mi*16 + g;
            int n = n0 + wn*32 + ni*8 + t*2;
            float b0v = bias[n], b1v = bias[n+1];
            float v0 = acc[mi][ni][0] + b0v;
            float v1 = acc[mi][ni][1] + b1v;
            float v2 = acc[mi][ni][2] + b0v;
            float v3 = acc[mi][ni][3] + b1v;
            if (relu) {
                v0 = v0 > 0.f ? v0 : 0.f; v1 = v1 > 0.f ? v1 : 0.f;
                v2 = v2 > 0.f ? v2 : 0.f; v3 = v3 > 0.f ? v3 : 0.f;
            }
            *(float2*)&C[m*N + n]       = make_float2(v0, v1);
            *(float2*)&C[(m+8)*N + n]   = make_float2(v2, v3);
        }
    }
}

// ---------------- persistent LSTM scan ----------------
#define NB_LSTM 32
__device__ __forceinline__ void grid_barrier() {
    __threadfence();
    __syncthreads();
    if (threadIdx.x == 0) {
        unsigned gen = g_bar_gen;
        if (atomicAdd(&g_bar_cnt, 1) == NB_LSTM - 1) {
            atomicExch(&g_bar_cnt, 0);
            __threadfence();
            g_bar_gen = gen + 1;
        } else {
            while (g_bar_gen == gen) { __nanosleep(40); }
        }
        __threadfence();
    }
    __syncthreads();
}

__global__ void __launch_bounds__(128, 1)
lstm_kernel(const float* __restrict__ gx, const float* __restrict__ done,
            const float* __restrict__ h0, const float* __restrict__ c0,
            const float* __restrict__ W_hh, const float* __restrict__ b_hh,
            float* __restrict__ out) {
    __shared__ float w_s[4][128][4];   // [gate][k][jl]
    __shared__ float h_sm[128*32];     // [k*32+b], masked h
    __shared__ float gacc[4][4][32];   // [gate][jl][b]
    __shared__ float c_s[4][32];
    __shared__ float d_s[32];
    __shared__ float bb_s[4][4];

    int q = blockIdx.x, tid = threadIdx.x;
    int j0 = q * 4;
    int gate = tid >> 5;               // also serves as jl in the epilogue
    int b = tid & 31;

    for (int i = tid; i < 2048; i += 128) {
        int jl = i & 3, k = (i >> 2) & 127, g = i >> 9;
        w_s[g][k][jl] = W_hh[(g*128 + j0 + jl)*128 + k];
    }
    if (tid < 16) bb_s[tid >> 2][tid & 3] = b_hh[(tid >> 2)*128 + j0 + (tid & 3)];
    c_s[gate][b] = c0[b*128 + j0 + gate];
    __stcg(&g_hA[(j0 + gate)*32 + b], h0[b*128 + j0 + gate]);
    grid_barrier();

    float last_h = 0.f, last_c = 0.f;
    for (int t = 0; t < TT; t++) {
        const float* hr = (t & 1) ? g_hB : g_hA;
        float*       hw = (t & 1) ? g_hA : g_hB;
        if (tid < 32) d_s[tid] = done[t*32 + tid];
        __syncthreads();
        for (int i = tid; i < 4096; i += 128)
            h_sm[i] = __ldcg(&hr[i]) * (1.f - d_s[i & 31]);
        __syncthreads();

        const float* gxr = &gx[(t*32 + b)*512 + gate*128 + j0];
        float a0 = gxr[0] + bb_s[gate][0];
        float a1 = gxr[1] + bb_s[gate][1];
        float a2 = gxr[2] + bb_s[gate][2];
        float a3 = gxr[3] + bb_s[gate][3];
        #pragma unroll 8
        for (int k = 0; k < 128; k++) {
            float hv = h_sm[k*32 + b];
            float4 w4 = *(const float4*)&w_s[gate][k][0];
            a0 += w4.x * hv; a1 += w4.y * hv; a2 += w4.z * hv; a3 += w4.w * hv;
        }
        gacc[gate][0][b] = a0; gacc[gate][1][b] = a1;
        gacc[gate][2][b] = a2; gacc[gate][3][b] = a3;
        __syncthreads();

        float iv = gacc[0][gate][b], fv = gacc[1][gate][b];
        float gv = gacc[2][gate][b], ov = gacc[3][gate][b];
        float cm = c_s[gate][b] * (1.f - d_s[b]);
        float cn = sigm(fv) * cm + sigm(iv) * tanhf(gv);
        float hn = sigm(ov) * tanhf(cn);
        c_s[gate][b] = cn;
        last_h = hn; last_c = cn;
        __stcg(&hw[(j0 + gate)*32 + b], hn);
        g_hs[(t*32 + b)*128 + j0 + gate] = hn;
        grid_barrier();
    }
    out[OFF_HT + b*128 + j0 + gate] = last_h;
    out[OFF_CT + b*128 + j0 + gate] = last_c;
}

// ---------------- heads: logits + value, warp-per-row ----------------
__global__ void heads_kernel(const float* __restrict__ Wa, const float* __restrict__ ba,
                             const float* __restrict__ Wc, const float* __restrict__ bc,
                             float* __restrict__ out) {
    __shared__ float wa_s[AA*HH];
    __shared__ float wc_s[HH];
    int tid = threadIdx.x;
    for (int i = tid; i < AA*HH; i += blockDim.x) wa_s[i] = Wa[i];
    for (int i = tid; i < HH; i += blockDim.x) wc_s[i] = Wc[i];
    __syncthreads();

    int warp = tid >> 5, lane = tid & 31;
    int n = blockIdx.x * 8 + warp;
    if (n >= NN) return;

    float la[AA];
    #pragma unroll
    for (int a = 0; a < AA; a++) la[a] = 0.f;
    float v = 0.f;
    #pragma unroll
    for (int kc = 0; kc < 4; kc++) {
        int k = kc*32 + lane;
        float hv = g_hs[n*HH + k];
        #pragma unroll
        for (int a = 0; a < AA; a++) la[a] += wa_s[a*HH + k] * hv;
        v += wc_s[k] * hv;
    }
    #pragma unroll
    for (int off = 16; off > 0; off >>= 1) {
        #pragma unroll
        for (int a = 0; a < AA; a++) la[a] += __shfl_xor_sync(0xffffffffu, la[a], off);
        v += __shfl_xor_sync(0xffffffffu, v, off);
    }
    if (lane < AA) out[OFF_LOGITS + n*AA + lane] = la[lane] + ba[lane];
    if (lane == AA) out[OFF_VALUE + n] = v + bc[0];
}

// ---------------- launcher ----------------
extern "C" void kernel_launch(void* const* d_in, const int* in_sizes, int n_in,
                              void* d_out, int out_size) {
    const float* x    = (const float*)d_in[0];
    const float* done = (const float*)d_in[1];
    const float* h0   = (const float*)d_in[2];
    const float* c0   = (const float*)d_in[3];
    const float* W1   = (const float*)d_in[4];
    const float* b1   = (const float*)d_in[5];
    const float* W2   = (const float*)d_in[6];
    const float* b2   = (const float*)d_in[7];
    const float* W3   = (const float*)d_in[8];
    const float* b3   = (const float*)d_in[9];
    const float* Wfc  = (const float*)d_in[10];
    const float* bfc  = (const float*)d_in[11];
    const float* W_ih = (const float*)d_in[12];
    const float* W_hh = (const float*)d_in[13];
    const float* b_ih = (const float*)d_in[14];
    const float* b_hh = (const float*)d_in[15];
    const float* Wa   = (const float*)d_in[16];
    const float* ba   = (const float*)d_in[17];
    const float* Wc   = (const float*)d_in[18];
    const float* bc   = (const float*)d_in[19];
    float* out = (float*)d_out;

    float* z3 = nullptr, *hid = nullptr, *gx = nullptr;
    cudaGetSymbolAddress((void**)&z3,  g_z3);
    cudaGetSymbolAddress((void**)&hid, g_hidden);
    cudaGetSymbolAddress((void**)&gx,  g_gx);

    prep_kernel<<<64, 256>>>(W1, W2, W3);
    conv1_kernel<<<NN, 320>>>(x, b1);
    conv2_kernel<<<NN, 160>>>(b2);
    conv3_kernel<<<NN, 128>>>(b3);
    gemm_tf32_nt_kernel<<<dim3(8, 32), 256>>>(z3,  Wfc,  bfc,  hid, NN, 512, 3136, 1);
    gemm_tf32_nt_kernel<<<dim3(8, 32), 256>>>(hid, W_ih, b_ih, gx,  NN, 512, 512,  0);
    lstm_kernel<<<NB_LSTM, 128>>>(gx, done, h0, c0, W_hh, b_hh, out);
    heads_kernel<<<512, 256>>>(Wa, ba, Wc, bc, out);
}

// round 11
// speedup vs baseline: 1.5868x; 1.2130x over previous
#include <cuda_runtime.h>
#include <math.h>
#include <stdint.h>

// ---------------- problem constants ----------------
#define TT 128
#define BB 32
#define NN (TT*BB)      // 4096
#define HH 128
#define AA 6

// output layout: logits (4096*6) | value (4096) | hT (32*128) | cT (32*128)
#define OFF_LOGITS 0
#define OFF_VALUE  24576
#define OFF_HT     28672
#define OFF_CT     32768

// ---------------- device scratch ----------------
__device__ float g_z1[NN*32*20*20];     // conv1 out
__device__ float g_z2[NN*64*9*9];       // conv2 out
__device__ float g_z3[NN*3136];         // conv3 out, flattened torch order
__device__ float g_hidden[NN*512];      // fc out
__device__ float g_gx[NN*512];          // gates_x
__device__ float g_hs[NN*HH];           // per-step hidden outputs
__device__ float g_hA[BB*HH];           // double-buffered h, layout [j*32+b]
__device__ float g_hB[BB*HH];
__device__ float g_w1t[64*32];          // [ky*8+kx][oc], pre-scaled by 1/255
__device__ float g_w2m[16*4*8*32*2];    // conv2 weights in mma B-fragment order, tf32-rounded
__device__ float g_w3t[576*64];         // [ic*9+ky*3+kx][oc]

__device__ int g_bar_cnt;               // zero-init; returns to 0 after each barrier
__device__ volatile unsigned g_bar_gen; // monotonic; equality-compared -> replay safe

__device__ __forceinline__ float sigm(float x) { return 1.f / (1.f + expf(-x)); }

// ---------------- cp.async helpers ----------------
__device__ __forceinline__ void cp16(uint32_t saddr, const void* gptr) {
    asm volatile("cp.async.cg.shared.global [%0], [%1], 16;" :: "r"(saddr), "l"(gptr));
}
#define CP_COMMIT() asm volatile("cp.async.commit_group;")
#define CP_WAIT(n)  asm volatile("cp.async.wait_group %0;" :: "n"(n))
__device__ __forceinline__ uint32_t s2u(const void* p) {
    return (uint32_t)__cvta_generic_to_shared(p);
}

// ---------------- tf32 mma helpers ----------------
__device__ __forceinline__ uint32_t f2tf(float f) {
    uint32_t u;
    asm("cvt.rna.tf32.f32 %0, %1;" : "=r"(u) : "f"(f));
    return u;
}
__device__ __forceinline__ void mma_tf32(float* d, const uint32_t* a, const uint32_t* b) {
    asm volatile(
        "mma.sync.aligned.m16n8k8.row.col.f32.tf32.tf32.f32 "
        "{%0,%1,%2,%3}, {%4,%5,%6,%7}, {%8,%9}, {%0,%1,%2,%3};\n"
        : "+f"(d[0]), "+f"(d[1]), "+f"(d[2]), "+f"(d[3])
        : "r"(a[0]), "r"(a[1]), "r"(a[2]), "r"(a[3]), "r"(b[0]), "r"(b[1]));
}

// ---------------- weight prep ----------------
// g_w2m fragment order: idx = ((((c*4 + s)*8 + ni)*32 + lane)*2 + j)
//   k_local = s*8 + (lane&3) + j*4;  ic = 2c + (k_local>>4);  r = k_local&15;
//   oc = ni*8 + (lane>>2);  value = tf32(W2[oc*512 + ic*16 + r])
__global__ void prep_kernel(const float* __restrict__ W1,
                            const float* __restrict__ W2,
                            const float* __restrict__ W3) {
    int i = blockIdx.x * blockDim.x + threadIdx.x;
    int stride = gridDim.x * blockDim.x;
    for (int t = i; t < 2048; t += stride) {          // W1: (32,1,8,8), fold /255
        int oc = t / 64, p = t % 64;
        g_w1t[p*32 + oc] = W1[oc*64 + p] * (1.f/255.f);
    }
    for (int t = i; t < 32768; t += stride) {         // W2 -> mma fragment order
        int j  = t & 1;
        int l  = (t >> 1) & 31;
        int ni = (t >> 6) & 7;
        int s  = (t >> 9) & 3;
        int c  = t >> 11;
        int k_local = s*8 + (l & 3) + j*4;
        int ic = 2*c + (k_local >> 4);
        int r  = k_local & 15;
        int oc = ni*8 + (l >> 2);
        g_w2m[t] = __uint_as_float(f2tf(W2[oc*512 + ic*16 + r]));
    }
    for (int t = i; t < 36864; t += stride) {         // W3: (64,64,3,3)
        int oc = t / 576, p = t % 576;
        g_w3t[p*64 + oc] = W3[oc*576 + p];
    }
}

// ---------------- conv1: (1,84,84) -> (32,20,20), k8 s4, relu ----------------
__global__ void __launch_bounds__(320, 2)
conv1_kernel(const float* __restrict__ x, const float* __restrict__ b1) {
    __shared__ __align__(16) float img[84*84];
    __shared__ __align__(16) float w_s[64*32];
    int n = blockIdx.x, tid = threadIdx.x;

    uint32_t img_s = s2u(img), ws_s = s2u(w_s);
    for (int i = tid; i < 1764; i += 320) cp16(img_s + i*16, x + n*7056 + i*4);
    for (int i = tid; i < 512;  i += 320) cp16(ws_s + i*16, g_w1t + i*4);
    CP_COMMIT();
    CP_WAIT(0);
    __syncthreads();

    int ocg = tid & 7;
    int oy  = (tid >> 3) % 20;
    int oxh = tid / 160;
    int oc0 = ocg * 4;

    float acc[4][10];
    #pragma unroll
    for (int m = 0; m < 4; m++)
        #pragma unroll
        for (int o = 0; o < 10; o++) acc[m][o] = 0.f;

    #pragma unroll
    for (int ky = 0; ky < 8; ky++) {
        const float* row = &img[(oy*4 + ky)*84 + oxh*40];
        float in_r[44];
        #pragma unroll
        for (int c = 0; c < 11; c++) {
            float4 v = *(const float4*)&row[c*4];
            in_r[c*4+0] = v.x; in_r[c*4+1] = v.y; in_r[c*4+2] = v.z; in_r[c*4+3] = v.w;
        }
        #pragma unroll
        for (int kx = 0; kx < 8; kx++) {
            float4 w4 = *(const float4*)&w_s[(ky*8 + kx)*32 + oc0];
            #pragma unroll
            for (int ox = 0; ox < 10; ox++) {
                float iv = in_r[ox*4 + kx];
                acc[0][ox] += w4.x * iv;
                acc[1][ox] += w4.y * iv;
                acc[2][ox] += w4.z * iv;
                acc[3][ox] += w4.w * iv;
            }
        }
    }
    #pragma unroll
    for (int m = 0; m < 4; m++) {
        int oc = oc0 + m;
        float bv = b1[oc];
        #pragma unroll
        for (int ox = 0; ox < 10; ox++) {
            float v = acc[m][ox] + bv;
            g_z1[((n*32 + oc)*20 + oy)*20 + oxh*10 + ox] = v > 0.f ? v : 0.f;
        }
    }
}

// ---------------- conv2 tf32 implicit GEMM: (32,20,20) -> (64,9,9), k4 s2, relu ----
// Per image: GEMM M=81 positions (pad 96), N=64 oc, K=512 (chunks of 2 ic = 32 k).
// 4096 blocks x 192 threads = 6 warps = 6 m-tiles. cp.async double-buffered chunks.
// Weights pre-laid in B-fragment order (g_w2m, tf32-rounded) -> one LDS.64 per mma.
__global__ void __launch_bounds__(192, 2)
conv2_kernel(const float* __restrict__ b2) {
    __shared__ __align__(16) float in_s[2][800];
    __shared__ __align__(16) float w_s[2][2048];
    int n = blockIdx.x, tid = threadIdx.x;
    int warp = tid >> 5, lane = tid & 31;
    int g = lane >> 2, t = lane & 3;

    int pr0 = warp*16 + g, pr1 = pr0 + 8;       // real row ids (for store guard)
    int p0 = pr0 > 80 ? 80 : pr0;
    int p1 = pr1 > 80 ? 80 : pr1;
    int base0 = (p0/9)*40 + (p0%9)*2;           // (2*oy)*20 + 2*ox
    int base1 = (p1/9)*40 + (p1%9)*2;

    float acc[8][4];
    #pragma unroll
    for (int ni = 0; ni < 8; ni++)
        #pragma unroll
        for (int r = 0; r < 4; r++) acc[ni][r] = 0.f;

    // prologue: stage chunk 0
    {
        uint32_t si = s2u(in_s[0]), sw = s2u(w_s[0]);
        for (int i = tid; i < 200; i += 192) cp16(si + i*16, g_z1 + n*12800 + i*4);
        for (int i = tid; i < 512; i += 192) cp16(sw + i*16, g_w2m + i*4);
        CP_COMMIT();
    }

    for (int c = 0; c < 16; c++) {
        if (c + 1 < 16) {
            int nb = (c + 1) & 1;
            uint32_t si = s2u(in_s[nb]), sw = s2u(w_s[nb]);
            for (int i = tid; i < 200; i += 192)
                cp16(si + i*16, g_z1 + n*12800 + (c+1)*800 + i*4);
            for (int i = tid; i < 512; i += 192)
                cp16(sw + i*16, g_w2m + (c+1)*2048 + i*4);
            CP_COMMIT();
            CP_WAIT(1);
        } else {
            CP_WAIT(0);
        }
        __syncthreads();
        int cb = c & 1;
        const float* ins = in_s[cb];
        const float* ws  = w_s[cb];
        #pragma unroll
        for (int s = 0; s < 4; s++) {
            int k_t  = s*8 + t;
            int k_t4 = k_t + 4;
            int ia = (k_t  >> 4)*400 + ((k_t  >> 2) & 3)*20 + (k_t  & 3);
            int ib = (k_t4 >> 4)*400 + ((k_t4 >> 2) & 3)*20 + (k_t4 & 3);
            uint32_t af[4];
            af[0] = f2tf(ins[ia + base0]);
            af[1] = f2tf(ins[ia + base1]);
            af[2] = f2tf(ins[ib + base0]);
            af[3] = f2tf(ins[ib + base1]);
            #pragma unroll
            for (int ni = 0; ni < 8; ni++) {
                uint2 bv = *(const uint2*)&ws[((s*8 + ni)*32 + lane)*2];
                mma_tf32(acc[ni], af, (const uint32_t*)&bv);
            }
        }
        __syncthreads();
    }

    // epilogue: bias + relu, guarded scalar stores
    #pragma unroll
    for (int ni = 0; ni < 8; ni++) {
        int oc = ni*8 + t*2;
        float b0v = b2[oc], b1v = b2[oc + 1];
        float v0 = acc[ni][0] + b0v;
        float v1 = acc[ni][1] + b1v;
        float v2 = acc[ni][2] + b0v;
        float v3 = acc[ni][3] + b1v;
        v0 = v0 > 0.f ? v0 : 0.f; v1 = v1 > 0.f ? v1 : 0.f;
        v2 = v2 > 0.f ? v2 : 0.f; v3 = v3 > 0.f ? v3 : 0.f;
        if (pr0 < 81) {
            g_z2[(n*64 + oc    )*81 + pr0] = v0;
            g_z2[(n*64 + oc + 1)*81 + pr0] = v1;
        }
        if (pr1 < 81) {
            g_z2[(n*64 + oc    )*81 + pr1] = v2;
            g_z2[(n*64 + oc + 1)*81 + pr1] = v3;
        }
    }
}

// ---------------- conv3: (64,9,9) -> (64,7,7), k3 s1, relu ----------------
#define C3_INF 648    // 8 ic * 81
#define C3_WF  4608   // 8 ic * 9 * 64
__global__ void __launch_bounds__(128, 5)
conv3_kernel(const float* __restrict__ b3) {
    __shared__ __align__(16) float in_s[2][C3_INF];
    __shared__ __align__(16) float w_s[2][C3_WF];
    int n = blockIdx.x, tid = threadIdx.x;
    int ocg = tid & 15;
    int oy  = tid >> 4;                 // valid when tid < 112
    int oc0 = ocg * 4;

    float acc[4][7];
    #pragma unroll
    for (int m = 0; m < 4; m++)
        #pragma unroll
        for (int o = 0; o < 7; o++) acc[m][o] = 0.f;

    {
        uint32_t si = s2u(in_s[0]), sw = s2u(w_s[0]);
        for (int i = tid; i < 162;  i += 128) cp16(si + i*16, g_z2 + n*5184 + i*4);
        for (int i = tid; i < 1152; i += 128) cp16(sw + i*16, g_w3t + i*4);
        CP_COMMIT();
    }

    for (int cc = 0; cc < 8; cc++) {
        if (cc + 1 < 8) {
            int nb = (cc + 1) & 1;
            uint32_t si = s2u(in_s[nb]), sw = s2u(w_s[nb]);
            for (int i = tid; i < 162;  i += 128)
                cp16(si + i*16, g_z2 + n*5184 + (cc+1)*648 + i*4);
            for (int i = tid; i < 1152; i += 128)
                cp16(sw + i*16, g_w3t + (cc+1)*4608 + i*4);
            CP_COMMIT();
            CP_WAIT(1);
        } else {
            CP_WAIT(0);
        }
        __syncthreads();
        int cb = cc & 1;
        if (tid < 112) {
            #pragma unroll
            for (int ic = 0; ic < 8; ic++) {
                #pragma unroll
                for (int ky = 0; ky < 3; ky++) {
                    const float* row = &in_s[cb][ic*81 + (oy + ky)*9];
                    float in_r[9];
                    #pragma unroll
                    for (int c = 0; c < 9; c++) in_r[c] = row[c];
                    #pragma unroll
                    for (int kx = 0; kx < 3; kx++) {
                        float4 w4 = *(const float4*)&w_s[cb][(ic*9 + ky*3 + kx)*64 + oc0];
                        #pragma unroll
                        for (int ox = 0; ox < 7; ox++) {
                            float iv = in_r[ox + kx];
                            acc[0][ox] += w4.x * iv;
                            acc[1][ox] += w4.y * iv;
                            acc[2][ox] += w4.z * iv;
                            acc[3][ox] += w4.w * iv;
                        }
                    }
                }
            }
        }
        __syncthreads();
    }
    if (tid < 112) {
        #pragma unroll
        for (int m = 0; m < 4; m++) {
            int oc = oc0 + m;
            float bv = b3[oc];
            #pragma unroll
            for (int ox = 0; ox < 7; ox++) {
                float v = acc[m][ox] + bv;
                g_z3[n*3136 + oc*49 + oy*7 + ox] = v > 0.f ? v : 0.f;
            }
        }
    }
}

// ---------------- tf32 NT GEMM: C[M,N] = act(A[M,K] @ B[N,K]^T + bias[N]) ----------------
__global__ void __launch_bounds__(256)
gemm_tf32_nt_kernel(const float* __restrict__ A, const float* __restrict__ B,
                    const float* __restrict__ bias, float* __restrict__ C,
                    int M, int N, int K, int relu) {
    __shared__ float As[16][132];
    __shared__ float Bs[16][68];
    int m0 = blockIdx.y * 128, n0 = blockIdx.x * 64;
    int tid = threadIdx.x;
    int warp = tid >> 5, lane = tid & 31;
    int wm = warp >> 1, wn = warp & 1;
    int g = lane >> 2, t = lane & 3;
    int sr = tid >> 2, sc = (tid & 3) * 4;

    float acc[2][4][4];
    #pragma unroll
    for (int mi = 0; mi < 2; mi++)
        #pragma unroll
        for (int ni = 0; ni < 4; ni++)
            #pragma unroll
            for (int r = 0; r < 4; r++) acc[mi][ni][r] = 0.f;

    const float* Ap0 = A + (m0 + sr) * K + sc;
    const float* Ap1 = A + (m0 + sr + 64) * K + sc;
    const float* Bp  = B + (n0 + sr) * K + sc;

    float4 a_f0 = *(const float4*)Ap0;
    float4 a_f1 = *(const float4*)Ap1;
    float4 b_f  = *(const float4*)Bp;

    for (int k0 = 0; k0 < K; k0 += 16) {
        As[sc+0][sr] = a_f0.x; As[sc+1][sr] = a_f0.y; As[sc+2][sr] = a_f0.z; As[sc+3][sr] = a_f0.w;
        As[sc+0][sr+64] = a_f1.x; As[sc+1][sr+64] = a_f1.y; As[sc+2][sr+64] = a_f1.z; As[sc+3][sr+64] = a_f1.w;
        Bs[sc+0][sr] = b_f.x; Bs[sc+1][sr] = b_f.y; Bs[sc+2][sr] = b_f.z; Bs[sc+3][sr] = b_f.w;
        __syncthreads();
        if (k0 + 16 < K) {
            a_f0 = *(const float4*)(Ap0 + k0 + 16);
            a_f1 = *(const float4*)(Ap1 + k0 + 16);
            b_f  = *(const float4*)(Bp  + k0 + 16);
        }
        #pragma unroll
        for (int kk = 0; kk < 16; kk += 8) {
            uint32_t af[2][4];
            #pragma unroll
            for (int mi = 0; mi < 2; mi++) {
                int m = wm*32 + mi*16;
                af[mi][0] = f2tf(As[kk + t    ][m + g    ]);
                af[mi][1] = f2tf(As[kk + t    ][m + g + 8]);
                af[mi][2] = f2tf(As[kk + t + 4][m + g    ]);
                af[mi][3] = f2tf(As[kk + t + 4][m + g + 8]);
            }
            uint32_t bf[4][2];
            #pragma unroll
            for (int ni = 0; ni < 4; ni++) {
                int nb = wn*32 + ni*8;
                bf[ni][0] = f2tf(Bs[kk + t    ][nb + g]);
                bf[ni][1] = f2tf(Bs[kk + t + 4][nb + g]);
            }
            #pragma unroll
            for (int mi = 0; mi < 2; mi++)
                #pragma unroll
                for (int ni = 0; ni < 4; ni++)
                    mma_tf32(acc[mi][ni], af[mi], bf[ni]);
        }
        __syncthreads();
    }

    #pragma unroll
    for (int mi = 0; mi < 2; mi++) {
        #pragma unroll
        for (int ni = 0; ni < 4; ni++) {
            int m = m0 + wm*32 + mi*16 + g;
            int n = n0 + wn*32 + ni*8 + t*2;
            float b0v = bias[n], b1v = bias[n+1];
            float v0 = acc[mi][ni][0] + b0v;
            float v1 = acc[mi][ni][1] + b1v;
            float v2 = acc[mi][ni][2] + b0v;
            float v3 = acc[mi][ni][3] + b1v;
            if (relu) {
                v0 = v0 > 0.f ? v0 : 0.f; v1 = v1 > 0.f ? v1 : 0.f;
                v2 = v2 > 0.f ? v2 : 0.f; v3 = v3 > 0.f ? v3 : 0.f;
            }
            *(float2*)&C[m*N + n]       = make_float2(v0, v1);
            *(float2*)&C[(m+8)*N + n]   = make_float2(v2, v3);
        }
    }
}

// ---------------- persistent LSTM scan ----------------
#define NB_LSTM 32
__device__ __forceinline__ void grid_barrier() {
    __threadfence();
    __syncthreads();
    if (threadIdx.x == 0) {
        unsigned gen = g_bar_gen;
        if (atomicAdd(&g_bar_cnt, 1) == NB_LSTM - 1) {
            atomicExch(&g_bar_cnt, 0);
            __threadfence();
            g_bar_gen = gen + 1;
        } else {
            while (g_bar_gen == gen) { __nanosleep(40); }
        }
        __threadfence();
    }
    __syncthreads();
}

__global__ void __launch_bounds__(128, 1)
lstm_kernel(const float* __restrict__ gx, const float* __restrict__ done,
            const float* __restrict__ h0, const float* __restrict__ c0,
            const float* __restrict__ W_hh, const float* __restrict__ b_hh,
            float* __restrict__ out) {
    __shared__ float w_s[4][128][4];   // [gate][k][jl]
    __shared__ float h_sm[128*32];     // [k*32+b], masked h
    __shared__ float gacc[4][4][32];   // [gate][jl][b]
    __shared__ float c_s[4][32];
    __shared__ float d_s[32];
    __shared__ float bb_s[4][4];

    int q = blockIdx.x, tid = threadIdx.x;
    int j0 = q * 4;
    int gate = tid >> 5;
    int b = tid & 31;

    for (int i = tid; i < 2048; i += 128) {
        int jl = i & 3, k = (i >> 2) & 127, g = i >> 9;
        w_s[g][k][jl] = W_hh[(g*128 + j0 + jl)*128 + k];
    }
    if (tid < 16) bb_s[tid >> 2][tid & 3] = b_hh[(tid >> 2)*128 + j0 + (tid & 3)];
    c_s[gate][b] = c0[b*128 + j0 + gate];
    __stcg(&g_hA[(j0 + gate)*32 + b], h0[b*128 + j0 + gate]);
    grid_barrier();

    float last_h = 0.f, last_c = 0.f;
    for (int t = 0; t < TT; t++) {
        const float* hr = (t & 1) ? g_hB : g_hA;
        float*       hw = (t & 1) ? g_hA : g_hB;
        if (tid < 32) d_s[tid] = done[t*32 + tid];
        __syncthreads();
        for (int i = tid; i < 4096; i += 128)
            h_sm[i] = __ldcg(&hr[i]) * (1.f - d_s[i & 31]);
        __syncthreads();

        const float* gxr = &gx[(t*32 + b)*512 + gate*128 + j0];
        float a0 = gxr[0] + bb_s[gate][0];
        float a1 = gxr[1] + bb_s[gate][1];
        float a2 = gxr[2] + bb_s[gate][2];
        float a3 = gxr[3] + bb_s[gate][3];
        #pragma unroll 8
        for (int k = 0; k < 128; k++) {
            float hv = h_sm[k*32 + b];
            float4 w4 = *(const float4*)&w_s[gate][k][0];
            a0 += w4.x * hv; a1 += w4.y * hv; a2 += w4.z * hv; a3 += w4.w * hv;
        }
        gacc[gate][0][b] = a0; gacc[gate][1][b] = a1;
        gacc[gate][2][b] = a2; gacc[gate][3][b] = a3;
        __syncthreads();

        float iv = gacc[0][gate][b], fv = gacc[1][gate][b];
        float gv = gacc[2][gate][b], ov = gacc[3][gate][b];
        float cm = c_s[gate][b] * (1.f - d_s[b]);
        float cn = sigm(fv) * cm + sigm(iv) * tanhf(gv);
        float hn = sigm(ov) * tanhf(cn);
        c_s[gate][b] = cn;
        last_h = hn; last_c = cn;
        __stcg(&hw[(j0 + gate)*32 + b], hn);
        g_hs[(t*32 + b)*128 + j0 + gate] = hn;
        grid_barrier();
    }
    out[OFF_HT + b*128 + j0 + gate] = last_h;
    out[OFF_CT + b*128 + j0 + gate] = last_c;
}

// ---------------- heads: logits + value, warp-per-row ----------------
__global__ void heads_kernel(const float* __restrict__ Wa, const float* __restrict__ ba,
                             const float* __restrict__ Wc, const float* __restrict__ bc,
                             float* __restrict__ out) {
    __shared__ float wa_s[AA*HH];
    __shared__ float wc_s[HH];
    int tid = threadIdx.x;
    for (int i = tid; i < AA*HH; i += blockDim.x) wa_s[i] = Wa[i];
    for (int i = tid; i < HH; i += blockDim.x) wc_s[i] = Wc[i];
    __syncthreads();

    int warp = tid >> 5, lane = tid & 31;
    int n = blockIdx.x * 8 + warp;
    if (n >= NN) return;

    float la[AA];
    #pragma unroll
    for (int a = 0; a < AA; a++) la[a] = 0.f;
    float v = 0.f;
    #pragma unroll
    for (int kc = 0; kc < 4; kc++) {
        int k = kc*32 + lane;
        float hv = g_hs[n*HH + k];
        #pragma unroll
        for (int a = 0; a < AA; a++) la[a] += wa_s[a*HH + k] * hv;
        v += wc_s[k] * hv;
    }
    #pragma unroll
    for (int off = 16; off > 0; off >>= 1) {
        #pragma unroll
        for (int a = 0; a < AA; a++) la[a] += __shfl_xor_sync(0xffffffffu, la[a], off);
        v += __shfl_xor_sync(0xffffffffu, v, off);
    }
    if (lane < AA) out[OFF_LOGITS + n*AA + lane] = la[lane] + ba[lane];
    if (lane == AA) out[OFF_VALUE + n] = v + bc[0];
}

// ---------------- launcher ----------------
extern "C" void kernel_launch(void* const* d_in, const int* in_sizes, int n_in,
                              void* d_out, int out_size) {
    const float* x    = (const float*)d_in[0];
    const float* done = (const float*)d_in[1];
    const float* h0   = (const float*)d_in[2];
    const float* c0   = (const float*)d_in[3];
    const float* W1   = (const float*)d_in[4];
    const float* b1   = (const float*)d_in[5];
    const float* W2   = (const float*)d_in[6];
    const float* b2   = (const float*)d_in[7];
    const float* W3   = (const float*)d_in[8];
    const float* b3   = (const float*)d_in[9];
    const float* Wfc  = (const float*)d_in[10];
    const float* bfc  = (const float*)d_in[11];
    const float* W_ih = (const float*)d_in[12];
    const float* W_hh = (const float*)d_in[13];
    const float* b_ih = (const float*)d_in[14];
    const float* b_hh = (const float*)d_in[15];
    const float* Wa   = (const float*)d_in[16];
    const float* ba   = (const float*)d_in[17];
    const float* Wc   = (const float*)d_in[18];
    const float* bc   = (const float*)d_in[19];
    float* out = (float*)d_out;

    float* z3 = nullptr, *hid = nullptr, *gx = nullptr;
    cudaGetSymbolAddress((void**)&z3,  g_z3);
    cudaGetSymbolAddress((void**)&hid, g_hidden);
    cudaGetSymbolAddress((void**)&gx,  g_gx);

    prep_kernel<<<64, 256>>>(W1, W2, W3);
    conv1_kernel<<<NN, 320>>>(x, b1);
    conv2_kernel<<<NN, 192>>>(b2);
    conv3_kernel<<<NN, 128>>>(b3);
    gemm_tf32_nt_kernel<<<dim3(8, 32), 256>>>(z3,  Wfc,  bfc,  hid, NN, 512, 3136, 1);
    gemm_tf32_nt_kernel<<<dim3(8, 32), 256>>>(hid, W_ih, b_ih, gx,  NN, 512, 512,  0);
    lstm_kernel<<<NB_LSTM, 128>>>(gx, done, h0, c0, W_hh, b_hh, out);
    heads_kernel<<<512, 256>>>(Wa, ba, Wc, bc, out);
}

// round 15
// speedup vs baseline: 1.7815x; 1.1227x over previous
#include <cuda_runtime.h>
#include <math.h>
#include <stdint.h>

// ---------------- problem constants ----------------
#define TT 128
#define BB 32
#define NN (TT*BB)      // 4096
#define HH 128
#define AA 6

// output layout: logits (4096*6) | value (4096) | hT (32*128) | cT (32*128)
#define OFF_LOGITS 0
#define OFF_VALUE  24576
#define OFF_HT     28672
#define OFF_CT     32768

// ---------------- device scratch ----------------
__device__ float g_z1[NN*32*20*20];     // conv1 out
__device__ float g_z2[NN*64*9*9];       // conv2 out
__device__ float g_z3[NN*3136];         // conv3 out, flattened torch order
__device__ float g_hidden[NN*512];      // fc out
__device__ float g_gx[NN*512];          // gates_x
__device__ float g_hs[NN*HH];           // per-step hidden outputs
__device__ float g_hA[BB*HH];           // double-buffered h, layout [j*32+b]
__device__ float g_hB[BB*HH];
__device__ float g_w1t[64*32];          // [ky*8+kx][oc], pre-scaled by 1/255
__device__ float g_w2m[16*4*8*32*2];    // conv2 weights in mma B-fragment order, tf32-rounded
__device__ float g_w3m[8*9*8*32*2];     // conv3 weights in mma B-fragment order, tf32-rounded

__device__ int g_bar_cnt;               // zero-init; returns to 0 after each barrier
__device__ volatile unsigned g_bar_gen; // monotonic; equality-compared -> replay safe

__device__ __forceinline__ float sigm(float x) { return 1.f / (1.f + expf(-x)); }

// ---------------- cp.async helpers ----------------
__device__ __forceinline__ void cp16(uint32_t saddr, const void* gptr) {
    asm volatile("cp.async.cg.shared.global [%0], [%1], 16;" :: "r"(saddr), "l"(gptr));
}
#define CP_COMMIT() asm volatile("cp.async.commit_group;")
#define CP_WAIT(n)  asm volatile("cp.async.wait_group %0;" :: "n"(n))
__device__ __forceinline__ uint32_t s2u(const void* p) {
    return (uint32_t)__cvta_generic_to_shared(p);
}

// ---------------- tf32 mma helpers ----------------
__device__ __forceinline__ uint32_t f2tf(float f) {
    uint32_t u;
    asm("cvt.rna.tf32.f32 %0, %1;" : "=r"(u) : "f"(f));
    return u;
}
__device__ __forceinline__ void mma_tf32(float* d, const uint32_t* a, const uint32_t* b) {
    asm volatile(
        "mma.sync.aligned.m16n8k8.row.col.f32.tf32.tf32.f32 "
        "{%0,%1,%2,%3}, {%4,%5,%6,%7}, {%8,%9}, {%0,%1,%2,%3};\n"
        : "+f"(d[0]), "+f"(d[1]), "+f"(d[2]), "+f"(d[3])
        : "r"(a[0]), "r"(a[1]), "r"(a[2]), "r"(a[3]), "r"(b[0]), "r"(b[1]));
}

// ---------------- weight prep ----------------
// g_w2m fragment order: idx = ((((c*4 + s)*8 + ni)*32 + lane)*2 + j)
//   k_local = s*8 + (lane&3) + j*4;  ic = 2c + (k_local>>4);  r = k_local&15;
//   oc = ni*8 + (lane>>2);  value = tf32(W2[oc*512 + ic*16 + r])
// g_w3m fragment order: idx = ((((c*9 + s)*8 + ni)*32 + lane)*2 + j)
//   k_local = s*8 + (lane&3) + j*4 (0..71);  ic = c*8 + k_local/9;  tap = k_local%9;
//   oc = ni*8 + (lane>>2);  value = tf32(W3[oc*576 + ic*9 + tap])
__global__ void prep_kernel(const float* __restrict__ W1,
                            const float* __restrict__ W2,
                            const float* __restrict__ W3) {
    int i = blockIdx.x * blockDim.x + threadIdx.x;
    int stride = gridDim.x * blockDim.x;
    for (int t = i; t < 2048; t += stride) {          // W1: (32,1,8,8), fold /255
        int oc = t / 64, p = t % 64;
        g_w1t[p*32 + oc] = W1[oc*64 + p] * (1.f/255.f);
    }
    for (int t = i; t < 32768; t += stride) {         // W2 -> mma fragment order
        int j  = t & 1;
        int l  = (t >> 1) & 31;
        int ni = (t >> 6) & 7;
        int s  = (t >> 9) & 3;
        int c  = t >> 11;
        int k_local = s*8 + (l & 3) + j*4;
        int ic = 2*c + (k_local >> 4);
        int r  = k_local & 15;
        int oc = ni*8 + (l >> 2);
        g_w2m[t] = __uint_as_float(f2tf(W2[oc*512 + ic*16 + r]));
    }
    for (int t = i; t < 36864; t += stride) {         // W3 -> mma fragment order
        int j  = t & 1;
        int l  = (t >> 1) & 31;
        int ni = (t >> 6) & 7;
        int s  = (t / 512) % 9;
        int c  = t / 4608;
        int k_local = s*8 + (l & 3) + j*4;            // 0..71
        int ic = c*8 + k_local / 9;
        int tap = k_local % 9;
        int oc = ni*8 + (l >> 2);
        g_w3m[t] = __uint_as_float(f2tf(W3[oc*576 + ic*9 + tap]));
    }
}

// ---------------- conv1: (1,84,84) -> (32,20,20), k8 s4, relu ----------------
__global__ void __launch_bounds__(320, 2)
conv1_kernel(const float* __restrict__ x, const float* __restrict__ b1) {
    __shared__ __align__(16) float img[84*84];
    __shared__ __align__(16) float w_s[64*32];
    int n = blockIdx.x, tid = threadIdx.x;

    uint32_t img_s = s2u(img), ws_s = s2u(w_s);
    for (int i = tid; i < 1764; i += 320) cp16(img_s + i*16, x + n*7056 + i*4);
    for (int i = tid; i < 512;  i += 320) cp16(ws_s + i*16, g_w1t + i*4);
    CP_COMMIT();
    CP_WAIT(0);
    __syncthreads();

    int ocg = tid & 7;
    int oy  = (tid >> 3) % 20;
    int oxh = tid / 160;
    int oc0 = ocg * 4;

    float acc[4][10];
    #pragma unroll
    for (int m = 0; m < 4; m++)
        #pragma unroll
        for (int o = 0; o < 10; o++) acc[m][o] = 0.f;

    #pragma unroll
    for (int ky = 0; ky < 8; ky++) {
        const float* row = &img[(oy*4 + ky)*84 + oxh*40];
        float in_r[44];
        #pragma unroll
        for (int c = 0; c < 11; c++) {
            float4 v = *(const float4*)&row[c*4];
            in_r[c*4+0] = v.x; in_r[c*4+1] = v.y; in_r[c*4+2] = v.z; in_r[c*4+3] = v.w;
        }
        #pragma unroll
        for (int kx = 0; kx < 8; kx++) {
            float4 w4 = *(const float4*)&w_s[(ky*8 + kx)*32 + oc0];
            #pragma unroll
            for (int ox = 0; ox < 10; ox++) {
                float iv = in_r[ox*4 + kx];
                acc[0][ox] += w4.x * iv;
                acc[1][ox] += w4.y * iv;
                acc[2][ox] += w4.z * iv;
                acc[3][ox] += w4.w * iv;
            }
        }
    }
    #pragma unroll
    for (int m = 0; m < 4; m++) {
        int oc = oc0 + m;
        float bv = b1[oc];
        #pragma unroll
        for (int ox = 0; ox < 10; ox++) {
            float v = acc[m][ox] + bv;
            g_z1[((n*32 + oc)*20 + oy)*20 + oxh*10 + ox] = v > 0.f ? v : 0.f;
        }
    }
}

// ---------------- conv2 tf32 implicit GEMM: (32,20,20) -> (64,9,9), k4 s2, relu ----
__global__ void __launch_bounds__(192, 2)
conv2_kernel(const float* __restrict__ b2) {
    __shared__ __align__(16) float in_s[2][800];
    __shared__ __align__(16) float w_s[2][2048];
    int n = blockIdx.x, tid = threadIdx.x;
    int warp = tid >> 5, lane = tid & 31;
    int g = lane >> 2, t = lane & 3;

    int pr0 = warp*16 + g, pr1 = pr0 + 8;       // real row ids (for store guard)
    int p0 = pr0 > 80 ? 80 : pr0;
    int p1 = pr1 > 80 ? 80 : pr1;
    int base0 = (p0/9)*40 + (p0%9)*2;           // (2*oy)*20 + 2*ox
    int base1 = (p1/9)*40 + (p1%9)*2;

    float acc[8][4];
    #pragma unroll
    for (int ni = 0; ni < 8; ni++)
        #pragma unroll
        for (int r = 0; r < 4; r++) acc[ni][r] = 0.f;

    {
        uint32_t si = s2u(in_s[0]), sw = s2u(w_s[0]);
        for (int i = tid; i < 200; i += 192) cp16(si + i*16, g_z1 + n*12800 + i*4);
        for (int i = tid; i < 512; i += 192) cp16(sw + i*16, g_w2m + i*4);
        CP_COMMIT();
    }

    for (int c = 0; c < 16; c++) {
        if (c + 1 < 16) {
            int nb = (c + 1) & 1;
            uint32_t si = s2u(in_s[nb]), sw = s2u(w_s[nb]);
            for (int i = tid; i < 200; i += 192)
                cp16(si + i*16, g_z1 + n*12800 + (c+1)*800 + i*4);
            for (int i = tid; i < 512; i += 192)
                cp16(sw + i*16, g_w2m + (c+1)*2048 + i*4);
            CP_COMMIT();
            CP_WAIT(1);
        } else {
            CP_WAIT(0);
        }
        __syncthreads();
        int cb = c & 1;
        const float* ins = in_s[cb];
        const float* ws  = w_s[cb];
        #pragma unroll
        for (int s = 0; s < 4; s++) {
            int k_t  = s*8 + t;
            int k_t4 = k_t + 4;
            int ia = (k_t  >> 4)*400 + ((k_t  >> 2) & 3)*20 + (k_t  & 3);
            int ib = (k_t4 >> 4)*400 + ((k_t4 >> 2) & 3)*20 + (k_t4 & 3);
            uint32_t af[4];
            af[0] = f2tf(ins[ia + base0]);
            af[1] = f2tf(ins[ia + base1]);
            af[2] = f2tf(ins[ib + base0]);
            af[3] = f2tf(ins[ib + base1]);
            #pragma unroll
            for (int ni = 0; ni < 8; ni++) {
                uint2 bv = *(const uint2*)&ws[((s*8 + ni)*32 + lane)*2];
                mma_tf32(acc[ni], af, (const uint32_t*)&bv);
            }
        }
        __syncthreads();
    }

    #pragma unroll
    for (int ni = 0; ni < 8; ni++) {
        int oc = ni*8 + t*2;
        float b0v = b2[oc], b1v = b2[oc + 1];
        float v0 = acc[ni][0] + b0v;
        float v1 = acc[ni][1] + b1v;
        float v2 = acc[ni][2] + b0v;
        float v3 = acc[ni][3] + b1v;
        v0 = v0 > 0.f ? v0 : 0.f; v1 = v1 > 0.f ? v1 : 0.f;
        v2 = v2 > 0.f ? v2 : 0.f; v3 = v3 > 0.f ? v3 : 0.f;
        if (pr0 < 81) {
            g_z2[(n*64 + oc    )*81 + pr0] = v0;
            g_z2[(n*64 + oc + 1)*81 + pr0] = v1;
        }
        if (pr1 < 81) {
            g_z2[(n*64 + oc    )*81 + pr1] = v2;
            g_z2[(n*64 + oc + 1)*81 + pr1] = v3;
        }
    }
}

// ---------------- conv3 tf32 implicit GEMM: (64,9,9) -> (64,7,7), k3 s1, relu ----
// Per image: GEMM M=49 positions (pad 64), N=64 oc, K=576 (8 chunks of 8 ic = 72 k).
// 4096 blocks x 128 threads = 4 warps = 4 m-tiles. cp.async double-buffered chunks.
// k packed as ic*9 + tap (576 = 72*8, no padding). A-addresses via per-thread
// offset table off[k] = ic_local*81 + ky*9 + kx, plus base(position).
__global__ void __launch_bounds__(128)
conv3_kernel(const float* __restrict__ b3) {
    __shared__ __align__(16) float in_s[2][648];
    __shared__ __align__(16) float w_s[2][4608];
    int n = blockIdx.x, tid = threadIdx.x;
    int warp = tid >> 5, lane = tid & 31;
    int g = lane >> 2, t = lane & 3;

    int pr0 = warp*16 + g, pr1 = pr0 + 8;       // real row ids (for store guard)
    int p0 = pr0 > 48 ? 48 : pr0;
    int p1 = pr1 > 48 ? 48 : pr1;
    int base0 = (p0/7)*9 + (p0%7);              // oy*9 + ox
    int base1 = (p1/7)*9 + (p1%7);

    // per-thread A k-offsets: k = s*8 + t (A), +4 (B); off = ic_l*81 + ky*9 + kx
    int offA[9], offB[9];
    #pragma unroll
    for (int s = 0; s < 9; s++) {
        int kA = s*8 + t, kB = kA + 4;
        int icA = kA/9, tapA = kA%9;
        int icB = kB/9, tapB = kB%9;
        offA[s] = icA*81 + (tapA/3)*9 + (tapA%3);
        offB[s] = icB*81 + (tapB/3)*9 + (tapB%3);
    }

    float acc[8][4];
    #pragma unroll
    for (int ni = 0; ni < 8; ni++)
        #pragma unroll
        for (int r = 0; r < 4; r++) acc[ni][r] = 0.f;

    {
        uint32_t si = s2u(in_s[0]), sw = s2u(w_s[0]);
        for (int i = tid; i < 162;  i += 128) cp16(si + i*16, g_z2 + n*5184 + i*4);
        for (int i = tid; i < 1152; i += 128) cp16(sw + i*16, g_w3m + i*4);
        CP_COMMIT();
    }

    for (int c = 0; c < 8; c++) {
        if (c + 1 < 8) {
            int nb = (c + 1) & 1;
            uint32_t si = s2u(in_s[nb]), sw = s2u(w_s[nb]);
            for (int i = tid; i < 162;  i += 128)
                cp16(si + i*16, g_z2 + n*5184 + (c+1)*648 + i*4);
            for (int i = tid; i < 1152; i += 128)
                cp16(sw + i*16, g_w3m + (c+1)*4608 + i*4);
            CP_COMMIT();
            CP_WAIT(1);
        } else {
            CP_WAIT(0);
        }
        __syncthreads();
        int cb = c & 1;
        const float* ins = in_s[cb];
        const float* ws  = w_s[cb];
        #pragma unroll
        for (int s = 0; s < 9; s++) {
            uint32_t af[4];
            af[0] = f2tf(ins[offA[s] + base0]);
            af[1] = f2tf(ins[offA[s] + base1]);
            af[2] = f2tf(ins[offB[s] + base0]);
            af[3] = f2tf(ins[offB[s] + base1]);
            #pragma unroll
            for (int ni = 0; ni < 8; ni++) {
                uint2 bv = *(const uint2*)&ws[((s*8 + ni)*32 + lane)*2];
                mma_tf32(acc[ni], af, (const uint32_t*)&bv);
            }
        }
        __syncthreads();
    }

    // epilogue: bias + relu, guarded scalar stores (g_z3[n][oc][p], p = oy*7+ox)
    #pragma unroll
    for (int ni = 0; ni < 8; ni++) {
        int oc = ni*8 + t*2;
        float b0v = b3[oc], b1v = b3[oc + 1];
        float v0 = acc[ni][0] + b0v;
        float v1 = acc[ni][1] + b1v;
        float v2 = acc[ni][2] + b0v;
        float v3 = acc[ni][3] + b1v;
        v0 = v0 > 0.f ? v0 : 0.f; v1 = v1 > 0.f ? v1 : 0.f;
        v2 = v2 > 0.f ? v2 : 0.f; v3 = v3 > 0.f ? v3 : 0.f;
        if (pr0 < 49) {
            g_z3[n*3136 + (oc    )*49 + pr0] = v0;
            g_z3[n*3136 + (oc + 1)*49 + pr0] = v1;
        }
        if (pr1 < 49) {
            g_z3[n*3136 + (oc    )*49 + pr1] = v2;
            g_z3[n*3136 + (oc + 1)*49 + pr1] = v3;
        }
    }
}

// ---------------- tf32 NT GEMM: C[M,N] = act(A[M,K] @ B[N,K]^T + bias[N]) ----------------
__global__ void __launch_bounds__(256)
gemm_tf32_nt_kernel(const float* __restrict__ A, const float* __restrict__ B,
                    const float* __restrict__ bias, float* __restrict__ C,
                    int M, int N, int K, int relu) {
    __shared__ float As[16][132];
    __shared__ float Bs[16][68];
    int m0 = blockIdx.y * 128, n0 = blockIdx.x * 64;
    int tid = threadIdx.x;
    int warp = tid >> 5, lane = tid & 31;
    int wm = warp >> 1, wn = warp & 1;
    int g = lane >> 2, t = lane & 3;
    int sr = tid >> 2, sc = (tid & 3) * 4;

    float acc[2][4][4];
    #pragma unroll
    for (int mi = 0; mi < 2; mi++)
        #pragma unroll
        for (int ni = 0; ni < 4; ni++)
            #pragma unroll
            for (int r = 0; r < 4; r++) acc[mi][ni][r] = 0.f;

    const float* Ap0 = A + (m0 + sr) * K + sc;
    const float* Ap1 = A + (m0 + sr + 64) * K + sc;
    const float* Bp  = B + (n0 + sr) * K + sc;

    float4 a_f0 = *(const float4*)Ap0;
    float4 a_f1 = *(const float4*)Ap1;
    float4 b_f  = *(const float4*)Bp;

    for (int k0 = 0; k0 < K; k0 += 16) {
        As[sc+0][sr] = a_f0.x; As[sc+1][sr] = a_f0.y; As[sc+2][sr] = a_f0.z; As[sc+3][sr] = a_f0.w;
        As[sc+0][sr+64] = a_f1.x; As[sc+1][sr+64] = a_f1.y; As[sc+2][sr+64] = a_f1.z; As[sc+3][sr+64] = a_f1.w;
        Bs[sc+0][sr] = b_f.x; Bs[sc+1][sr] = b_f.y; Bs[sc+2][sr] = b_f.z; Bs[sc+3][sr] = b_f.w;
        __syncthreads();
        if (k0 + 16 < K) {
            a_f0 = *(const float4*)(Ap0 + k0 + 16);
            a_f1 = *(const float4*)(Ap1 + k0 + 16);
            b_f  = *(const float4*)(Bp  + k0 + 16);
        }
        #pragma unroll
        for (int kk = 0; kk < 16; kk += 8) {
            uint32_t af[2][4];
            #pragma unroll
            for (int mi = 0; mi < 2; mi++) {
                int m = wm*32 + mi*16;
                af[mi][0] = f2tf(As[kk + t    ][m + g    ]);
                af[mi][1] = f2tf(As[kk + t    ][m + g + 8]);
                af[mi][2] = f2tf(As[kk + t + 4][m + g    ]);
                af[mi][3] = f2tf(As[kk + t + 4][m + g + 8]);
            }
            uint32_t bf[4][2];
            #pragma unroll
            for (int ni = 0; ni < 4; ni++) {
                int nb = wn*32 + ni*8;
                bf[ni][0] = f2tf(Bs[kk + t    ][nb + g]);
                bf[ni][1] = f2tf(Bs[kk + t + 4][nb + g]);
            }
            #pragma unroll
            for (int mi = 0; mi < 2; mi++)
                #pragma unroll
                for (int ni = 0; ni < 4; ni++)
                    mma_tf32(acc[mi][ni], af[mi], bf[ni]);
        }
        __syncthreads();
    }

    #pragma unroll
    for (int mi = 0; mi < 2; mi++) {
        #pragma unroll
        for (int ni = 0; ni < 4; ni++) {
            int m = m0 + wm*32 + mi*16 + g;
            int n = n0 + wn*32 + ni*8 + t*2;
            float b0v = bias[n], b1v = bias[n+1];
            float v0 = acc[mi][ni][0] + b0v;
            float v1 = acc[mi][ni][1] + b1v;
            float v2 = acc[mi][ni][2] + b0v;
            float v3 = acc[mi][ni][3] + b1v;
            if (relu) {
                v0 = v0 > 0.f ? v0 : 0.f; v1 = v1 > 0.f ? v1 : 0.f;
                v2 = v2 > 0.f ? v2 : 0.f; v3 = v3 > 0.f ? v3 : 0.f;
            }
            *(float2*)&C[m*N + n]       = make_float2(v0, v1);
            *(float2*)&C[(m+8)*N + n]   = make_float2(v2, v3);
        }
    }
}

// ---------------- persistent LSTM scan ----------------
#define NB_LSTM 32
__device__ __forceinline__ void grid_barrier() {
    __threadfence();
    __syncthreads();
    if (threadIdx.x == 0) {
        unsigned gen = g_bar_gen;
        if (atomicAdd(&g_bar_cnt, 1) == NB_LSTM - 1) {
            atomicExch(&g_bar_cnt, 0);
            __threadfence();
            g_bar_gen = gen + 1;
        } else {
            while (g_bar_gen == gen) { __nanosleep(40); }
        }
        __threadfence();
    }
    __syncthreads();
}

__global__ void __launch_bounds__(128, 1)
lstm_kernel(const float* __restrict__ gx, const float* __restrict__ done,
            const float* __restrict__ h0, const float* __restrict__ c0,
            const float* __restrict__ W_hh, const float* __restrict__ b_hh,
            float* __restrict__ out) {
    __shared__ float w_s[4][128][4];   // [gate][k][jl]
    __shared__ float h_sm[128*32];     // [k*32+b], masked h
    __shared__ float gacc[4][4][32];   // [gate][jl][b]
    __shared__ float c_s[4][32];
    __shared__ float d_s[32];
    __shared__ float bb_s[4][4];

    int q = blockIdx.x, tid = threadIdx.x;
    int j0 = q * 4;
    int gate = tid >> 5;
    int b = tid & 31;

    for (int i = tid; i < 2048; i += 128) {
        int jl = i & 3, k = (i >> 2) & 127, g = i >> 9;
        w_s[g][k][jl] = W_hh[(g*128 + j0 + jl)*128 + k];
    }
    if (tid < 16) bb_s[tid >> 2][tid & 3] = b_hh[(tid >> 2)*128 + j0 + (tid & 3)];
    c_s[gate][b] = c0[b*128 + j0 + gate];
    __stcg(&g_hA[(j0 + gate)*32 + b], h0[b*128 + j0 + gate]);
    grid_barrier();

    float last_h = 0.f, last_c = 0.f;
    for (int t = 0; t < TT; t++) {
        const float* hr = (t & 1) ? g_hB : g_hA;
        float*       hw = (t & 1) ? g_hA : g_hB;
        if (tid < 32) d_s[tid] = done[t*32 + tid];
        __syncthreads();
        for (int i = tid; i < 4096; i += 128)
            h_sm[i] = __ldcg(&hr[i]) * (1.f - d_s[i & 31]);
        __syncthreads();

        const float* gxr = &gx[(t*32 + b)*512 + gate*128 + j0];
        float a0 = gxr[0] + bb_s[gate][0];
        float a1 = gxr[1] + bb_s[gate][1];
        float a2 = gxr[2] + bb_s[gate][2];
        float a3 = gxr[3] + bb_s[gate][3];
        #pragma unroll 8
        for (int k = 0; k < 128; k++) {
            float hv = h_sm[k*32 + b];
            float4 w4 = *(const float4*)&w_s[gate][k][0];
            a0 += w4.x * hv; a1 += w4.y * hv; a2 += w4.z * hv; a3 += w4.w * hv;
        }
        gacc[gate][0][b] = a0; gacc[gate][1][b] = a1;
        gacc[gate][2][b] = a2; gacc[gate][3][b] = a3;
        __syncthreads();

        float iv = gacc[0][gate][b], fv = gacc[1][gate][b];
        float gv = gacc[2][gate][b], ov = gacc[3][gate][b];
        float cm = c_s[gate][b] * (1.f - d_s[b]);
        float cn = sigm(fv) * cm + sigm(iv) * tanhf(gv);
        float hn = sigm(ov) * tanhf(cn);
        c_s[gate][b] = cn;
        last_h = hn; last_c = cn;
        __stcg(&hw[(j0 + gate)*32 + b], hn);
        g_hs[(t*32 + b)*128 + j0 + gate] = hn;
        grid_barrier();
    }
    out[OFF_HT + b*128 + j0 + gate] = last_h;
    out[OFF_CT + b*128 + j0 + gate] = last_c;
}

// ---------------- heads: logits + value, warp-per-row ----------------
__global__ void heads_kernel(const float* __restrict__ Wa, const float* __restrict__ ba,
                             const float* __restrict__ Wc, const float* __restrict__ bc,
                             float* __restrict__ out) {
    __shared__ float wa_s[AA*HH];
    __shared__ float wc_s[HH];
    int tid = threadIdx.x;
    for (int i = tid; i < AA*HH; i += blockDim.x) wa_s[i] = Wa[i];
    for (int i = tid; i < HH; i += blockDim.x) wc_s[i] = Wc[i];
    __syncthreads();

    int warp = tid >> 5, lane = tid & 31;
    int n = blockIdx.x * 8 + warp;
    if (n >= NN) return;

    float la[AA];
    #pragma unroll
    for (int a = 0; a < AA; a++) la[a] = 0.f;
    float v = 0.f;
    #pragma unroll
    for (int kc = 0; kc < 4; kc++) {
        int k = kc*32 + lane;
        float hv = g_hs[n*HH + k];
        #pragma unroll
        for (int a = 0; a < AA; a++) la[a] += wa_s[a*HH + k] * hv;
        v += wc_s[k] * hv;
    }
    #pragma unroll
    for (int off = 16; off > 0; off >>= 1) {
        #pragma unroll
        for (int a = 0; a < AA; a++) la[a] += __shfl_xor_sync(0xffffffffu, la[a], off);
        v += __shfl_xor_sync(0xffffffffu, v, off);
    }
    if (lane < AA) out[OFF_LOGITS + n*AA + lane] = la[lane] + ba[lane];
    if (lane == AA) out[OFF_VALUE + n] = v + bc[0];
}

// ---------------- launcher ----------------
extern "C" void kernel_launch(void* const* d_in, const int* in_sizes, int n_in,
                              void* d_out, int out_size) {
    const float* x    = (const float*)d_in[0];
    const float* done = (const float*)d_in[1];
    const float* h0   = (const float*)d_in[2];
    const float* c0   = (const float*)d_in[3];
    const float* W1   = (const float*)d_in[4];
    const float* b1   = (const float*)d_in[5];
    const float* W2   = (const float*)d_in[6];
    const float* b2   = (const float*)d_in[7];
    const float* W3   = (const float*)d_in[8];
    const float* b3   = (const float*)d_in[9];
    const float* Wfc  = (const float*)d_in[10];
    const float* bfc  = (const float*)d_in[11];
    const float* W_ih = (const float*)d_in[12];
    const float* W_hh = (const float*)d_in[13];
    const float* b_ih = (const float*)d_in[14];
    const float* b_hh = (const float*)d_in[15];
    const float* Wa   = (const float*)d_in[16];
    const float* ba   = (const float*)d_in[17];
    const float* Wc   = (const float*)d_in[18];
    const float* bc   = (const float*)d_in[19];
    float* out = (float*)d_out;

    float* z3 = nullptr, *hid = nullptr, *gx = nullptr;
    cudaGetSymbolAddress((void**)&z3,  g_z3);
    cudaGetSymbolAddress((void**)&hid, g_hidden);
    cudaGetSymbolAddress((void**)&gx,  g_gx);

    prep_kernel<<<64, 256>>>(W1, W2, W3);
    conv1_kernel<<<NN, 320>>>(x, b1);
    conv2_kernel<<<NN, 192>>>(b2);
    conv3_kernel<<<NN, 128>>>(b3);
    gemm_tf32_nt_kernel<<<dim3(8, 32), 256>>>(z3,  Wfc,  bfc,  hid, NN, 512, 3136, 1);
    gemm_tf32_nt_kernel<<<dim3(8, 32), 256>>>(hid, W_ih, b_ih, gx,  NN, 512, 512,  0);
    lstm_kernel<<<NB_LSTM, 128>>>(gx, done, h0, c0, W_hh, b_hh, out);
    heads_kernel<<<512, 256>>>(Wa, ba, Wc, bc, out);
}